// round 1
// baseline (speedup 1.0000x reference)
#include <cuda_runtime.h>
#include <math.h>

#define BATCH 2
#define NHEAD 8
#define DM 512
#define HD 512
#define TT 8
#define HH 28
#define WWW 28
#define LL 6273          // 1 + 8*28*28
#define LP 1569          // 1 + 8*14*14
#define NP 1568
#define BHN 16           // BATCH*NHEAD
#define ATT_SCALE 0.04419417382415922f   // 1/sqrt(512)

// ---------------- scratch (static device allocations) ----------------
__device__ float g_Q[BHN * LL * HD];        // 205.6 MB
__device__ float g_K[BHN * LL * HD];
__device__ float g_V[BHN * LL * HD];
__device__ float g_PQ[BHN * LP * HD];       // 51.4 MB
__device__ float g_PK[BHN * LP * HD];
__device__ float g_PV[BHN * LP * HD];
__device__ float g_PVt[BHN * HD * LP];
__device__ float g_Kmod[BHN * LP * HD];
__device__ float g_logits[BHN * LP * LP];   // 157.6 MB
__device__ float g_att[BHN * LP * HD];
__device__ float g_PX[BATCH * LP * HD];
__device__ float g_emb[NP * HD];
__device__ float g_y[BATCH * LP * HD];

__device__ __forceinline__ float* qkv_out_ptr(int s) {
    return s == 0 ? g_Q : (s == 1 ? g_K : g_V);
}
__device__ __forceinline__ const float* pool_in_ptr(int s, const float* x) {
    return s == 0 ? g_Q : (s == 1 ? g_K : (s == 2 ? g_V : x));
}
__device__ __forceinline__ float* pool_out_ptr(int s) {
    return s == 0 ? g_PQ : (s == 1 ? g_PK : (s == 2 ? g_PV : g_PX));
}

// ---------------- generic 128x128x8 SGEMM template ----------------
// C[m,n] = sum_k a(z,m,k) * b(z,n,k); epilogue via op.store.
template <class OP>
__global__ void __launch_bounds__(256) gemm_k(OP op) {
    __shared__ float As[8][132];
    __shared__ float Bs[8][132];
    const int z  = blockIdx.z;
    const int bm = blockIdx.y * 128;
    const int bn = blockIdx.x * 128;
    const int tid = threadIdx.x;
    const int tx = tid & 15;
    const int ty = tid >> 4;

    float acc[8][8];
#pragma unroll
    for (int i = 0; i < 8; i++)
#pragma unroll
        for (int j = 0; j < 8; j++) acc[i][j] = 0.f;

    for (int k0 = 0; k0 < op.K; k0 += 8) {
#pragma unroll
        for (int i = 0; i < 4; i++) {
            int e = tid + i * 256;
            int m = e >> 3, kk = e & 7;
            int gk = k0 + kk;
            int gm = bm + m;
            As[kk][m] = (gm < op.M && gk < op.K) ? op.a(z, gm, gk) : 0.f;
            int gn = bn + m;
            Bs[kk][m] = (gn < op.N && gk < op.K) ? op.b(z, gn, gk) : 0.f;
        }
        __syncthreads();
#pragma unroll
        for (int kk = 0; kk < 8; kk++) {
            float ar[8], br[8];
            *(float4*)&ar[0] = *(const float4*)&As[kk][ty * 4];
            *(float4*)&ar[4] = *(const float4*)&As[kk][64 + ty * 4];
            *(float4*)&br[0] = *(const float4*)&Bs[kk][tx * 4];
            *(float4*)&br[4] = *(const float4*)&Bs[kk][64 + tx * 4];
#pragma unroll
            for (int i = 0; i < 8; i++)
#pragma unroll
                for (int j = 0; j < 8; j++) acc[i][j] += ar[i] * br[j];
        }
        __syncthreads();
    }
#pragma unroll
    for (int i = 0; i < 8; i++) {
        int gm = bm + ((i < 4) ? ty * 4 + i : 64 + ty * 4 + (i - 4));
        if (gm >= op.M) continue;
#pragma unroll
        for (int j = 0; j < 8; j++) {
            int gn = bn + ((j < 4) ? tx * 4 + j : 64 + tx * 4 + (j - 4));
            if (gn >= op.N) continue;
            op.store(z, gm, gn, acc[i][j]);
        }
    }
}

// ---------------- GEMM operand functors ----------------
// 1) QKV projection: (B*L, 512) x (4096, 512)^T -> scatter to (b,h,l,c)
struct OpQKV {
    const float* x; const float* W; const float* bias;
    int sel; int M, N, K;
    __device__ __forceinline__ float a(int, int m, int k) const { return x[m * DM + k]; }
    __device__ __forceinline__ float b(int, int n, int k) const { return W[n * DM + k]; }
    __device__ __forceinline__ void store(int, int m, int n, float v) const {
        int bb = m / LL, l = m % LL;
        int h = n >> 9, c = n & 511;
        qkv_out_ptr(sel)[((bb * NHEAD + h) * LL + l) * HD + c] = v + bias[n];
    }
};

// 2) Pooling conv as im2col GEMM: per image z, M=1568 out tokens, N=512, K=2048
struct OpPool {
    const float* x; const float* w;
    int selIn, selOut; int M, N, K;
    __device__ __forceinline__ float a(int z, int m, int k) const {
        int t = m / 196, rem = m % 196;
        int hy = rem / 14, wx = rem % 14;
        int patch = k >> 9, ci = k & 511;
        int dy = patch >> 1, dx = patch & 1;
        int l = 1 + ((t * HH + 2 * hy + dy) * WWW + (2 * wx + dx));
        return pool_in_ptr(selIn, x)[(z * LL + l) * HD + ci];
    }
    __device__ __forceinline__ float b(int, int n, int k) const {
        int ci = k & 511, patch = k >> 9;
        return w[n * 2048 + ci * 4 + patch];
    }
    __device__ __forceinline__ void store(int z, int m, int n, float v) const {
        pool_out_ptr(selOut)[(z * LP + 1 + m) * HD + n] = v;
    }
};

// 3) logits = PQ @ Kmod^T  (per image z; M=N=LP, K=512)
struct OpLogits {
    int M, N, K;
    __device__ __forceinline__ float a(int z, int m, int k) const {
        return g_PQ[(z * LP + m) * HD + k];
    }
    __device__ __forceinline__ float b(int z, int n, int k) const {
        return g_Kmod[(z * LP + n) * HD + k];
    }
    __device__ __forceinline__ void store(int z, int m, int n, float v) const {
        g_logits[(z * LP + m) * LP + n] = v;
    }
};

// 4) out = attn @ PV + (q==0 ? 1 : 2) * PQ   (per image z; M=LP, N=512, K=LP)
struct OpAV {
    int M, N, K;
    __device__ __forceinline__ float a(int z, int m, int k) const {
        return g_logits[(z * LP + m) * LP + k];
    }
    __device__ __forceinline__ float b(int z, int n, int k) const {
        return g_PVt[(z * HD + n) * LP + k];
    }
    __device__ __forceinline__ void store(int z, int m, int n, float v) const {
        float pq = g_PQ[(z * LP + m) * HD + n];
        g_att[(z * LP + m) * HD + n] = v + (m == 0 ? 1.f : 2.f) * pq;
    }
};

// 5) y = stacked @ Wd^T + bd + PX   (M = B*LP, N=512, K=4096)
struct OpY {
    const float* Wd; const float* bd;
    int M, N, K;
    __device__ __forceinline__ float a(int, int m, int k) const {
        int bb = m / LP, q = m % LP;
        int h = k >> 9, c = k & 511;
        return g_att[((bb * NHEAD + h) * LP + q) * HD + c];
    }
    __device__ __forceinline__ float b(int, int n, int k) const {
        return Wd[n * (NHEAD * HD) + k];
    }
    __device__ __forceinline__ void store(int, int m, int n, float v) const {
        g_y[m * DM + n] = v + bd[n] + g_PX[m * DM + n];
    }
};

// ---------------- small kernels ----------------
__global__ void cls_copy_k(int sel, const float* x, int nimg) {
    int i = blockIdx.x * 256 + threadIdx.x;
    if (i >= nimg * HD) return;
    int z = i >> 9, c = i & 511;
    pool_out_ptr(sel)[z * LP * HD + c] = pool_in_ptr(sel, x)[z * LL * HD + c];
}

__global__ void emb_k() {
    int i = blockIdx.x * 256 + threadIdx.x;
    if (i >= NP * HD) return;
    int tok = i >> 9, d = i & 511;
    int t = tok / 196, rem = tok % 196;
    int hy = rem / 14, wx = rem % 14;
    float pos; int j, half;
    if (d < 170)      { pos = (float)t;  j = d;        half = 85; }
    else if (d < 340) { pos = (float)hy; j = d - 170;  half = 85; }
    else              { pos = (float)wx; j = d - 340;  half = 86; }
    bool is_cos = (j >= half);
    int jj = is_cos ? j - half : j;
    float omega = powf(10000.f, -(float)jj / (float)half);
    float ang = pos * omega;
    g_emb[i] = is_cos ? cosf(ang) : sinf(ang);
}

__global__ void kmod_k() {
    int i = blockIdx.x * 256 + threadIdx.x;
    if (i >= BHN * LP * HD) return;
    int c = i & 511;
    int kpos = (i >> 9) % LP;
    float v = g_PK[i] * ATT_SCALE;
    if (kpos >= 1) v += g_emb[(kpos - 1) * HD + c];
    g_Kmod[i] = v;
}

// repair row q=0: logits[z,0,n] = scale * PQ[z,0]·PK[z,n]  (no emb term)
__global__ void row0_k() {
    int w = (blockIdx.x * blockDim.x + threadIdx.x) >> 5;
    int lane = threadIdx.x & 31;
    if (w >= BHN * LP) return;
    int z = w / LP, n = w % LP;
    const float* q = g_PQ + z * LP * HD;
    const float* kk = g_PK + (z * LP + n) * HD;
    float s = 0.f;
    for (int i = lane; i < HD; i += 32) s += q[i] * kk[i];
#pragma unroll
    for (int o = 16; o; o >>= 1) s += __shfl_xor_sync(0xffffffffu, s, o);
    if (lane == 0) g_logits[z * LP * LP + n] = s * ATT_SCALE;
}

__global__ void softmax_k() {
    int row = blockIdx.x;               // BHN*LP rows
    float* p = g_logits + (long long)row * LP;
    int tid = threadIdx.x;
    float v[7];
    float m = -1e30f;
#pragma unroll
    for (int i = 0; i < 7; i++) {
        int idx = tid + i * 256;
        v[i] = (idx < LP) ? p[idx] : -1e30f;
        m = fmaxf(m, v[i]);
    }
    __shared__ float red[256];
    red[tid] = m; __syncthreads();
    for (int s = 128; s > 0; s >>= 1) {
        if (tid < s) red[tid] = fmaxf(red[tid], red[tid + s]);
        __syncthreads();
    }
    m = red[0]; __syncthreads();
    float sum = 0.f;
#pragma unroll
    for (int i = 0; i < 7; i++) {
        int idx = tid + i * 256;
        v[i] = (idx < LP) ? expf(v[i] - m) : 0.f;
        sum += v[i];
    }
    red[tid] = sum; __syncthreads();
    for (int s = 128; s > 0; s >>= 1) {
        if (tid < s) red[tid] += red[tid + s];
        __syncthreads();
    }
    float inv = 1.f / red[0];
#pragma unroll
    for (int i = 0; i < 7; i++) {
        int idx = tid + i * 256;
        if (idx < LP) p[idx] = v[i] * inv;
    }
}

__global__ void transpose_pv_k() {
    int i = blockIdx.x * 256 + threadIdx.x;
    if (i >= BHN * HD * LP) return;
    int k = i % LP;
    int rest = i / LP;
    int c = rest & 511;
    int z = rest >> 9;
    g_PVt[i] = g_PV[(z * LP + k) * HD + c];
}

__global__ void ln_k(const float* gamma, const float* beta, float* out) {
    int row = blockIdx.x;               // B*LP rows
    const float* p = g_y + row * DM;
    int tid = threadIdx.x;              // 128 threads, 4 elems each
    float v[4];
#pragma unroll
    for (int i = 0; i < 4; i++) v[i] = p[tid + i * 128];
    __shared__ float red[128];
    float s = v[0] + v[1] + v[2] + v[3];
    red[tid] = s; __syncthreads();
    for (int st = 64; st > 0; st >>= 1) {
        if (tid < st) red[tid] += red[tid + st];
        __syncthreads();
    }
    float mu = red[0] / (float)DM;
    __syncthreads();
    float sq = 0.f;
#pragma unroll
    for (int i = 0; i < 4; i++) { float d = v[i] - mu; sq += d * d; }
    red[tid] = sq; __syncthreads();
    for (int st = 64; st > 0; st >>= 1) {
        if (tid < st) red[tid] += red[tid + st];
        __syncthreads();
    }
    float inv = rsqrtf(red[0] / (float)DM + 1e-5f);
    __syncthreads();
#pragma unroll
    for (int i = 0; i < 4; i++) {
        int c = tid + i * 128;
        out[row * DM + c] = (v[i] - mu) * inv * gamma[c] + beta[c];
    }
}

// ---------------- launch ----------------
extern "C" void kernel_launch(void* const* d_in, const int* in_sizes, int n_in,
                              void* d_out, int out_size) {
    const float* x    = (const float*)d_in[0];
    const float* Wq   = (const float*)d_in[1];
    const float* bq   = (const float*)d_in[2];
    const float* Wk   = (const float*)d_in[3];
    const float* bk   = (const float*)d_in[4];
    const float* Wv   = (const float*)d_in[5];
    const float* bv   = (const float*)d_in[6];
    const float* wpq  = (const float*)d_in[7];
    const float* wpk  = (const float*)d_in[8];
    const float* wpv  = (const float*)d_in[9];
    const float* wpx  = (const float*)d_in[10];
    const float* Wd   = (const float*)d_in[11];
    const float* bd   = (const float*)d_in[12];
    const float* gamma= (const float*)d_in[13];
    const float* beta = (const float*)d_in[14];
    float* out = (float*)d_out;

    // 1) QKV projections
    {
        OpQKV op; op.x = x; op.M = BATCH * LL; op.N = NHEAD * HD; op.K = DM;
        dim3 g((op.N + 127) / 128, (op.M + 127) / 128, 1);
        op.W = Wq; op.bias = bq; op.sel = 0; gemm_k<<<g, 256>>>(op);
        op.W = Wk; op.bias = bk; op.sel = 1; gemm_k<<<g, 256>>>(op);
        op.W = Wv; op.bias = bv; op.sel = 2; gemm_k<<<g, 256>>>(op);
    }
    // 2) pooling convs (im2col GEMM) + cls passthrough
    {
        OpPool op; op.x = x; op.M = NP; op.N = HD; op.K = 2048;
        dim3 g(4, (NP + 127) / 128, BHN);
        op.w = wpq; op.selIn = 0; op.selOut = 0; gemm_k<<<g, 256>>>(op);
        op.w = wpk; op.selIn = 1; op.selOut = 1; gemm_k<<<g, 256>>>(op);
        op.w = wpv; op.selIn = 2; op.selOut = 2; gemm_k<<<g, 256>>>(op);
        dim3 gx(4, (NP + 127) / 128, BATCH);
        op.w = wpx; op.selIn = 3; op.selOut = 3; gemm_k<<<gx, 256>>>(op);
    }
    cls_copy_k<<<(BHN * HD + 255) / 256, 256>>>(0, x, BHN);
    cls_copy_k<<<(BHN * HD + 255) / 256, 256>>>(1, x, BHN);
    cls_copy_k<<<(BHN * HD + 255) / 256, 256>>>(2, x, BHN);
    cls_copy_k<<<(BATCH * HD + 255) / 256, 256>>>(3, x, BATCH);

    // 3) positional embedding + Kmod = scale*PK + emb
    emb_k<<<(NP * HD + 255) / 256, 256>>>();
    kmod_k<<<(BHN * LP * HD + 255) / 256, 256>>>();

    // 4) logits GEMM, then repair row 0, softmax
    {
        OpLogits op; op.M = LP; op.N = LP; op.K = HD;
        dim3 g((LP + 127) / 128, (LP + 127) / 128, BHN);
        gemm_k<<<g, 256>>>(op);
    }
    row0_k<<<(BHN * LP * 32 + 255) / 256, 256>>>();
    softmax_k<<<BHN * LP, 256>>>();

    // 5) attn @ PV (+residual PQ)
    transpose_pv_k<<<(BHN * HD * LP + 255) / 256, 256>>>();
    {
        OpAV op; op.M = LP; op.N = HD; op.K = LP;
        dim3 g((HD + 127) / 128, (LP + 127) / 128, BHN);
        gemm_k<<<g, 256>>>(op);
    }

    // 6) output projection + bias + PX, then LayerNorm
    {
        OpY op; op.Wd = Wd; op.bd = bd; op.M = BATCH * LP; op.N = DM; op.K = NHEAD * HD;
        dim3 g((DM + 127) / 128, (op.M + 127) / 128, 1);
        gemm_k<<<g, 256>>>(op);
    }
    ln_k<<<BATCH * LP, 128>>>(gamma, beta, out);
}

// round 3
// speedup vs baseline: 2.4963x; 2.4963x over previous
#include <cuda_runtime.h>
#include <math.h>

#define BATCH 2
#define NHEAD 8
#define DM 512
#define HD 512
#define TT 8
#define HH 28
#define WWW 28
#define LL 6273          // 1 + 8*28*28
#define LP 1569          // 1 + 8*14*14
#define NP 1568
#define BHN 16           // BATCH*NHEAD
#define ATT_SCALE 0.04419417382415922f   // 1/sqrt(512)

// ---------------- scratch (static device allocations) ----------------
__device__ float g_Q[BHN * LL * HD];
__device__ float g_K[BHN * LL * HD];
__device__ float g_V[BHN * LL * HD];
__device__ float g_PQ[BHN * LP * HD];
__device__ float g_PK[BHN * LP * HD];
__device__ float g_PV[BHN * LP * HD];
__device__ float g_PVt[BHN * HD * LP];
__device__ float g_Kmod[BHN * LP * HD];
__device__ float g_logits[BHN * LP * LP];
__device__ float g_att[BHN * LP * HD];
__device__ float g_PX[BATCH * LP * HD];
__device__ float g_emb[NP * HD];
__device__ float g_y[BATCH * LP * HD];

__device__ __forceinline__ float* qkv_out_ptr(int s) {
    return s == 0 ? g_Q : (s == 1 ? g_K : g_V);
}
__device__ __forceinline__ const float* pool_in_ptr(int s, const float* x) {
    return s == 0 ? g_Q : (s == 1 ? g_K : (s == 2 ? g_V : x));
}
__device__ __forceinline__ float* pool_out_ptr(int s) {
    return s == 0 ? g_PQ : (s == 1 ? g_PK : (s == 2 ? g_PV : g_PX));
}

// ---------------- tf32 helpers ----------------
__device__ __forceinline__ unsigned f2tf32(float v) {
    unsigned r;
    asm("cvt.rna.tf32.f32 %0, %1;" : "=r"(r) : "f"(v));
    return r;
}
// 5-bit bijective swizzle on k; conflict-free for both STS (k spans lanes)
// and fragment LDS (m spans 8 via bits 0-2, k-quad spans bits 3-4).
__device__ __forceinline__ int swz(int k) {
    return ((k & 3) << 3) | (k >> 2);
}

// ---------------- tf32 tensor-core GEMM: 128x128x32, 256 threads ----------------
// C[m,n] = sum_k a(z,m,k) * b(z,n,k); epilogue via op.store.
template <class OP>
__global__ void __launch_bounds__(256) gemm_tc(OP op) {
    __shared__ unsigned As[32 * 128];
    __shared__ unsigned Bs[32 * 128];

    const int z  = blockIdx.z;
    const int bm = blockIdx.y * 128;
    const int bn = blockIdx.x * 128;
    const int tid  = threadIdx.x;
    const int lane = tid & 31;
    const int wid  = tid >> 5;
    const int wm = (wid >> 2) * 64;     // warp m offset: 0 or 64
    const int wn = (wid & 3) * 32;      // warp n offset: 0..96
    const int r = lane >> 2;            // 0..7
    const int c = lane & 3;             // 0..3

    const int lk = tid & 31;            // loader: k within tile (coalesced)
    const int lm = tid >> 5;            // loader: 0..7

    float acc[4][4][4];
#pragma unroll
    for (int i = 0; i < 4; i++)
#pragma unroll
        for (int j = 0; j < 4; j++)
#pragma unroll
            for (int e = 0; e < 4; e++) acc[i][j][e] = 0.f;

    float ra[16], rb[16];
    const int nkb = (op.K + 31) / 32;

    // fetch tile kb into registers
    auto fetch = [&](int kb) {
        int gk = kb * 32 + lk;
        bool kok = gk < op.K;
#pragma unroll
        for (int i = 0; i < 16; i++) {
            int m = lm * 16 + i;
            int gm = bm + m;
            ra[i] = (kok && gm < op.M) ? op.a(z, gm, gk) : 0.f;
            int gn = bn + m;
            rb[i] = (kok && gn < op.N) ? op.b(z, gn, gk) : 0.f;
        }
    };
    auto sts = [&]() {
        int col_x = swz(lk);
#pragma unroll
        for (int i = 0; i < 16; i++) {
            int m = lm * 16 + i;
            As[lk * 128 + (m ^ col_x)] = f2tf32(ra[i]);
            Bs[lk * 128 + (m ^ col_x)] = f2tf32(rb[i]);
        }
    };

    fetch(0);
    sts();

    for (int kb = 0; kb < nkb; kb++) {
        __syncthreads();                       // tile kb visible in smem
        if (kb + 1 < nkb) fetch(kb + 1);       // prefetch next (LDGs in flight)

#pragma unroll
        for (int ks = 0; ks < 32; ks += 8) {
            const int k0 = ks + c;
            const int k1 = ks + 4 + c;
            const int f0 = swz(k0), f1 = swz(k1);
            unsigned af[4][4], bf[4][2];
#pragma unroll
            for (int mt = 0; mt < 4; mt++) {
                int m = wm + mt * 16 + r;
                af[mt][0] = As[k0 * 128 + (m ^ f0)];
                af[mt][1] = As[k0 * 128 + ((m + 8) ^ f0)];
                af[mt][2] = As[k1 * 128 + (m ^ f1)];
                af[mt][3] = As[k1 * 128 + ((m + 8) ^ f1)];
            }
#pragma unroll
            for (int nt = 0; nt < 4; nt++) {
                int n = wn + nt * 8 + r;
                bf[nt][0] = Bs[k0 * 128 + (n ^ f0)];
                bf[nt][1] = Bs[k1 * 128 + (n ^ f1)];
            }
#pragma unroll
            for (int mt = 0; mt < 4; mt++)
#pragma unroll
                for (int nt = 0; nt < 4; nt++) {
                    asm volatile(
                        "mma.sync.aligned.m16n8k8.row.col.f32.tf32.tf32.f32 "
                        "{%0,%1,%2,%3}, {%4,%5,%6,%7}, {%8,%9}, {%0,%1,%2,%3};\n"
                        : "+f"(acc[mt][nt][0]), "+f"(acc[mt][nt][1]),
                          "+f"(acc[mt][nt][2]), "+f"(acc[mt][nt][3])
                        : "r"(af[mt][0]), "r"(af[mt][1]), "r"(af[mt][2]), "r"(af[mt][3]),
                          "r"(bf[nt][0]), "r"(bf[nt][1]));
                }
        }

        __syncthreads();                       // all reads of tile kb done
        if (kb + 1 < nkb) sts();               // write next tile
    }

    // epilogue
#pragma unroll
    for (int mt = 0; mt < 4; mt++) {
        int m0 = bm + wm + mt * 16 + r;
#pragma unroll
        for (int nt = 0; nt < 4; nt++) {
            int n0 = bn + wn + nt * 8 + 2 * c;
            if (m0 < op.M) {
                if (n0     < op.N) op.store(z, m0, n0,     acc[mt][nt][0]);
                if (n0 + 1 < op.N) op.store(z, m0, n0 + 1, acc[mt][nt][1]);
            }
            if (m0 + 8 < op.M) {
                if (n0     < op.N) op.store(z, m0 + 8, n0,     acc[mt][nt][2]);
                if (n0 + 1 < op.N) op.store(z, m0 + 8, n0 + 1, acc[mt][nt][3]);
            }
        }
    }
}

// ---------------- GEMM operand functors ----------------
struct OpQKV {
    const float* x; const float* W; const float* bias;
    int sel; int M, N, K;
    __device__ __forceinline__ float a(int, int m, int k) const { return x[m * DM + k]; }
    __device__ __forceinline__ float b(int, int n, int k) const { return W[n * DM + k]; }
    __device__ __forceinline__ void store(int, int m, int n, float v) const {
        int bb = m / LL, l = m % LL;
        int h = n >> 9, cc = n & 511;
        qkv_out_ptr(sel)[((bb * NHEAD + h) * LL + l) * HD + cc] = v + bias[n];
    }
};

struct OpPool {
    const float* x; const float* w;
    int selIn, selOut; int M, N, K;
    __device__ __forceinline__ float a(int z, int m, int k) const {
        int t = m / 196, rem = m % 196;
        int hy = rem / 14, wx = rem % 14;
        int patch = k >> 9, ci = k & 511;
        int dy = patch >> 1, dx = patch & 1;
        int l = 1 + ((t * HH + 2 * hy + dy) * WWW + (2 * wx + dx));
        return pool_in_ptr(selIn, x)[(z * LL + l) * HD + ci];
    }
    __device__ __forceinline__ float b(int, int n, int k) const {
        int ci = k & 511, patch = k >> 9;
        return w[n * 2048 + ci * 4 + patch];
    }
    __device__ __forceinline__ void store(int z, int m, int n, float v) const {
        pool_out_ptr(selOut)[(z * LP + 1 + m) * HD + n] = v;
    }
};

struct OpLogits {
    int M, N, K;
    __device__ __forceinline__ float a(int z, int m, int k) const {
        return g_PQ[(z * LP + m) * HD + k];
    }
    __device__ __forceinline__ float b(int z, int n, int k) const {
        return g_Kmod[(z * LP + n) * HD + k];
    }
    __device__ __forceinline__ void store(int z, int m, int n, float v) const {
        g_logits[(z * LP + m) * LP + n] = v;
    }
};

struct OpAV {
    int M, N, K;
    __device__ __forceinline__ float a(int z, int m, int k) const {
        return g_logits[(z * LP + m) * LP + k];
    }
    __device__ __forceinline__ float b(int z, int n, int k) const {
        return g_PVt[(z * HD + n) * LP + k];
    }
    __device__ __forceinline__ void store(int z, int m, int n, float v) const {
        float pq = g_PQ[(z * LP + m) * HD + n];
        g_att[(z * LP + m) * HD + n] = v + (m == 0 ? 1.f : 2.f) * pq;
    }
};

struct OpY {
    const float* Wd; const float* bd;
    int M, N, K;
    __device__ __forceinline__ float a(int, int m, int k) const {
        int bb = m / LP, q = m % LP;
        int h = k >> 9, cc = k & 511;
        return g_att[((bb * NHEAD + h) * LP + q) * HD + cc];
    }
    __device__ __forceinline__ float b(int, int n, int k) const {
        return Wd[n * (NHEAD * HD) + k];
    }
    __device__ __forceinline__ void store(int, int m, int n, float v) const {
        g_y[m * DM + n] = v + bd[n] + g_PX[m * DM + n];
    }
};

// ---------------- small kernels ----------------
__global__ void cls_copy_k(int sel, const float* x, int nimg) {
    int i = blockIdx.x * 256 + threadIdx.x;
    if (i >= nimg * HD) return;
    int z = i >> 9, cc = i & 511;
    pool_out_ptr(sel)[z * LP * HD + cc] = pool_in_ptr(sel, x)[z * LL * HD + cc];
}

__global__ void emb_k() {
    int i = blockIdx.x * 256 + threadIdx.x;
    if (i >= NP * HD) return;
    int tok = i >> 9, d = i & 511;
    int t = tok / 196, rem = tok % 196;
    int hy = rem / 14, wx = rem % 14;
    float pos; int j, half;
    if (d < 170)      { pos = (float)t;  j = d;        half = 85; }
    else if (d < 340) { pos = (float)hy; j = d - 170;  half = 85; }
    else              { pos = (float)wx; j = d - 340;  half = 86; }
    bool is_cos = (j >= half);
    int jj = is_cos ? j - half : j;
    float omega = powf(10000.f, -(float)jj / (float)half);
    float ang = pos * omega;
    g_emb[i] = is_cos ? cosf(ang) : sinf(ang);
}

__global__ void kmod_k() {
    int i = blockIdx.x * 256 + threadIdx.x;
    if (i >= BHN * LP * HD) return;
    int cc = i & 511;
    int kpos = (i >> 9) % LP;
    float v = g_PK[i] * ATT_SCALE;
    if (kpos >= 1) v += g_emb[(kpos - 1) * HD + cc];
    g_Kmod[i] = v;
}

__global__ void row0_k() {
    int w = (blockIdx.x * blockDim.x + threadIdx.x) >> 5;
    int lane = threadIdx.x & 31;
    if (w >= BHN * LP) return;
    int z = w / LP, n = w % LP;
    const float* q = g_PQ + z * LP * HD;
    const float* kk = g_PK + (z * LP + n) * HD;
    float s = 0.f;
    for (int i = lane; i < HD; i += 32) s += q[i] * kk[i];
#pragma unroll
    for (int o = 16; o; o >>= 1) s += __shfl_xor_sync(0xffffffffu, s, o);
    if (lane == 0) g_logits[z * LP * LP + n] = s * ATT_SCALE;
}

__global__ void softmax_k() {
    int row = blockIdx.x;
    float* p = g_logits + (long long)row * LP;
    int tid = threadIdx.x;
    float v[7];
    float m = -1e30f;
#pragma unroll
    for (int i = 0; i < 7; i++) {
        int idx = tid + i * 256;
        v[i] = (idx < LP) ? p[idx] : -1e30f;
        m = fmaxf(m, v[i]);
    }
    __shared__ float red[256];
    red[tid] = m; __syncthreads();
    for (int s = 128; s > 0; s >>= 1) {
        if (tid < s) red[tid] = fmaxf(red[tid], red[tid + s]);
        __syncthreads();
    }
    m = red[0]; __syncthreads();
    float sum = 0.f;
#pragma unroll
    for (int i = 0; i < 7; i++) {
        int idx = tid + i * 256;
        v[i] = (idx < LP) ? expf(v[i] - m) : 0.f;
        sum += v[i];
    }
    red[tid] = sum; __syncthreads();
    for (int s = 128; s > 0; s >>= 1) {
        if (tid < s) red[tid] += red[tid + s];
        __syncthreads();
    }
    float inv = 1.f / red[0];
#pragma unroll
    for (int i = 0; i < 7; i++) {
        int idx = tid + i * 256;
        if (idx < LP) p[idx] = v[i] * inv;
    }
}

__global__ void transpose_pv_k() {
    int i = blockIdx.x * 256 + threadIdx.x;
    if (i >= BHN * HD * LP) return;
    int k = i % LP;
    int rest = i / LP;
    int cc = rest & 511;
    int z = rest >> 9;
    g_PVt[i] = g_PV[(z * LP + k) * HD + cc];
}

__global__ void ln_k(const float* gamma, const float* beta, float* out) {
    int row = blockIdx.x;
    const float* p = g_y + row * DM;
    int tid = threadIdx.x;
    float v[4];
#pragma unroll
    for (int i = 0; i < 4; i++) v[i] = p[tid + i * 128];
    __shared__ float red[128];
    float s = v[0] + v[1] + v[2] + v[3];
    red[tid] = s; __syncthreads();
    for (int st = 64; st > 0; st >>= 1) {
        if (tid < st) red[tid] += red[tid + st];
        __syncthreads();
    }
    float mu = red[0] / (float)DM;
    __syncthreads();
    float sq = 0.f;
#pragma unroll
    for (int i = 0; i < 4; i++) { float d = v[i] - mu; sq += d * d; }
    red[tid] = sq; __syncthreads();
    for (int st = 64; st > 0; st >>= 1) {
        if (tid < st) red[tid] += red[tid + st];
        __syncthreads();
    }
    float inv = rsqrtf(red[0] / (float)DM + 1e-5f);
    __syncthreads();
#pragma unroll
    for (int i = 0; i < 4; i++) {
        int cc = tid + i * 128;
        out[row * DM + cc] = (v[i] - mu) * inv * gamma[cc] + beta[cc];
    }
}

// ---------------- launch ----------------
extern "C" void kernel_launch(void* const* d_in, const int* in_sizes, int n_in,
                              void* d_out, int out_size) {
    const float* x    = (const float*)d_in[0];
    const float* Wq   = (const float*)d_in[1];
    const float* bq   = (const float*)d_in[2];
    const float* Wk   = (const float*)d_in[3];
    const float* bk   = (const float*)d_in[4];
    const float* Wv   = (const float*)d_in[5];
    const float* bv   = (const float*)d_in[6];
    const float* wpq  = (const float*)d_in[7];
    const float* wpk  = (const float*)d_in[8];
    const float* wpv  = (const float*)d_in[9];
    const float* wpx  = (const float*)d_in[10];
    const float* Wd   = (const float*)d_in[11];
    const float* bd   = (const float*)d_in[12];
    const float* gamma= (const float*)d_in[13];
    const float* beta = (const float*)d_in[14];
    float* out = (float*)d_out;

    // 1) QKV projections
    {
        OpQKV op; op.x = x; op.M = BATCH * LL; op.N = NHEAD * HD; op.K = DM;
        dim3 g((op.N + 127) / 128, (op.M + 127) / 128, 1);
        op.W = Wq; op.bias = bq; op.sel = 0; gemm_tc<<<g, 256>>>(op);
        op.W = Wk; op.bias = bk; op.sel = 1; gemm_tc<<<g, 256>>>(op);
        op.W = Wv; op.bias = bv; op.sel = 2; gemm_tc<<<g, 256>>>(op);
    }
    // 2) pooling convs (im2col GEMM) + cls passthrough
    {
        OpPool op; op.x = x; op.M = NP; op.N = HD; op.K = 2048;
        dim3 g(4, (NP + 127) / 128, BHN);
        op.w = wpq; op.selIn = 0; op.selOut = 0; gemm_tc<<<g, 256>>>(op);
        op.w = wpk; op.selIn = 1; op.selOut = 1; gemm_tc<<<g, 256>>>(op);
        op.w = wpv; op.selIn = 2; op.selOut = 2; gemm_tc<<<g, 256>>>(op);
        dim3 gx(4, (NP + 127) / 128, BATCH);
        op.w = wpx; op.selIn = 3; op.selOut = 3; gemm_tc<<<gx, 256>>>(op);
    }
    cls_copy_k<<<(BHN * HD + 255) / 256, 256>>>(0, x, BHN);
    cls_copy_k<<<(BHN * HD + 255) / 256, 256>>>(1, x, BHN);
    cls_copy_k<<<(BHN * HD + 255) / 256, 256>>>(2, x, BHN);
    cls_copy_k<<<(BATCH * HD + 255) / 256, 256>>>(3, x, BATCH);

    // 3) positional embedding + Kmod = scale*PK + emb
    emb_k<<<(NP * HD + 255) / 256, 256>>>();
    kmod_k<<<(BHN * LP * HD + 255) / 256, 256>>>();

    // 4) logits GEMM, then repair row 0, softmax
    {
        OpLogits op; op.M = LP; op.N = LP; op.K = HD;
        dim3 g((LP + 127) / 128, (LP + 127) / 128, BHN);
        gemm_tc<<<g, 256>>>(op);
    }
    row0_k<<<(BHN * LP * 32 + 255) / 256, 256>>>();
    softmax_k<<<BHN * LP, 256>>>();

    // 5) attn @ PV (+residual PQ)
    transpose_pv_k<<<(BHN * HD * LP + 255) / 256, 256>>>();
    {
        OpAV op; op.M = LP; op.N = HD; op.K = LP;
        dim3 g((HD + 127) / 128, (LP + 127) / 128, BHN);
        gemm_tc<<<g, 256>>>(op);
    }

    // 6) output projection + bias + PX, then LayerNorm
    {
        OpY op; op.Wd = Wd; op.bd = bd; op.M = BATCH * LP; op.N = DM; op.K = NHEAD * HD;
        dim3 g((DM + 127) / 128, (op.M + 127) / 128, 1);
        gemm_tc<<<g, 256>>>(op);
    }
    ln_k<<<BATCH * LP, 128>>>(gamma, beta, out);
}

// round 6
// speedup vs baseline: 3.9533x; 1.5837x over previous
#include <cuda_runtime.h>
#include <math.h>
#include <stdint.h>

#define BATCH 2
#define NHEAD 8
#define DM 512
#define HD 512
#define TT 8
#define HH 28
#define WWW 28
#define LL 6273          // 1 + 8*28*28
#define LP 1569          // 1 + 8*14*14
#define LPP 1600         // padded K for attention GEMMs
#define NP 1568
#define BHN 16           // BATCH*NHEAD
#define ATT_SCALE 0.04419417382415922f   // 1/sqrt(512)

// ---------------- scratch (static device allocations, tf32-rounded where noted) ----------------
__device__ __align__(256) float g_xr  [BATCH * LL * DM];       // rounded x
__device__ __align__(256) float g_Wqr [NHEAD * HD * DM];
__device__ __align__(256) float g_Wkr [NHEAD * HD * DM];
__device__ __align__(256) float g_Wvr [NHEAD * HD * DM];
__device__ __align__(256) float g_Wdr [DM * NHEAD * HD];
__device__ __align__(256) float g_wp  [4][HD * 2048];          // packed+rounded pool weights
__device__ __align__(256) float g_Q   [BHN * LL * HD];         // rounded (pool GEMM input)
__device__ __align__(256) float g_K   [BHN * LL * HD];
__device__ __align__(256) float g_V   [BHN * LL * HD];
__device__ __align__(256) float g_PQ  [BHN * LP * HD];         // raw (residual / row0)
__device__ __align__(256) float g_PQr [BHN * LP * HD];         // rounded (logits a-input)
__device__ __align__(256) float g_PK  [BHN * LP * HD];         // raw (row0 / kmod)
__device__ __align__(256) float g_PV  [BHN * LP * HD];         // raw
__device__ __align__(256) float g_PVt [BHN * HD * LPP];        // rounded, k-padded
__device__ __align__(256) float g_Kmod[BHN * LP * HD];         // rounded
__device__ __align__(256) float g_logits[BHN * LP * LPP];      // stride LPP
__device__ __align__(256) float g_att [BHN * LP * HD];         // rounded (+residual)
__device__ __align__(256) float g_PX  [BATCH * LP * HD];       // raw
__device__ __align__(256) float g_emb [NP * HD];
__device__ __align__(256) float g_y   [BATCH * LP * HD];

__device__ __forceinline__ float* qkv_out_ptr(int s) {
    return s == 0 ? g_Q : (s == 1 ? g_K : g_V);
}
__device__ __forceinline__ const float* pool_in_ptr(int s, const float* x) {
    return s == 0 ? g_Q : (s == 1 ? g_K : (s == 2 ? g_V : x));
}
__device__ __forceinline__ float* pool_out_ptr(int s) {
    return s == 0 ? g_PQ : (s == 1 ? g_PK : (s == 2 ? g_PV : g_PX));
}

__device__ __forceinline__ float rnd32(float v) {
    unsigned u;
    asm("cvt.rna.tf32.f32 %0, %1;" : "=r"(u) : "f"(v));
    return __uint_as_float(u);
}

__device__ __forceinline__ void cp16(uint32_t dst, const float* src, bool valid) {
    if (valid)
        asm volatile("cp.async.cg.shared.global [%0], [%1], 16;\n" :: "r"(dst), "l"(src));
    else
        asm volatile("cp.async.cg.shared.global [%0], [%1], 16, %2;\n" :: "r"(dst), "l"(src), "r"(0));
}

// ---------------- tf32 tensor-core GEMM: 128x128x16 tiles, cp.async double-buffered ----------------
// C[m,n] = sum_k a[m,k]*b[n,k]; operands pre-rounded tf32; epilogue via op.store.
// smem per stage per side: 128 rows x (16 + 4 pad) floats.
#define RS 20
template <class OP>
__global__ void __launch_bounds__(256, 2) gemm_tc(OP op) {
    __shared__ float sm[4 * 128 * RS];      // [stage][A|B][128][RS]
    __shared__ int aT[128], bT[128];

    const int z  = blockIdx.z;
    const int bm = blockIdx.y * 128;
    const int bn = blockIdx.x * 128;
    const int tid = threadIdx.x, lane = tid & 31;
    const int wid = tid >> 5;
    const int wm = (wid >> 2) * 64, wn = (wid & 3) * 32;
    const int r = lane >> 2, c = lane & 3;

    if (tid < 128) { int gm = bm + tid; aT[tid] = (gm < op.M) ? op.arow(z, gm) : -1; }
    else           { int gn = bn + tid - 128; bT[tid - 128] = (gn < op.N) ? op.brow(z, gn) : -1; }
    __syncthreads();

    const float* aB = op.abase(z);
    const float* bB = op.bbase(z);

    const int kq = tid & 3;                 // k-quad 0..3 (16 k per tile)
    const int mr = tid >> 2;                // 0..63
    const int ao0 = aT[mr], ao1 = aT[mr + 64];
    const int bo0 = bT[mr], bo1 = bT[mr + 64];

    const uint32_t smu = (uint32_t)__cvta_generic_to_shared(sm);
    const uint32_t d0 = (uint32_t)(mr * RS + kq * 4) * 4u;
    const uint32_t d1 = (uint32_t)((mr + 64) * RS + kq * 4) * 4u;

    float acc[4][4][4];
#pragma unroll
    for (int i = 0; i < 4; i++)
#pragma unroll
        for (int j = 0; j < 4; j++)
#pragma unroll
            for (int e = 0; e < 4; e++) acc[i][j][e] = 0.f;

    auto FETCH = [&](int kb, int st) {
        int gk = kb * 16 + kq * 4;
        int ak = op.akoff(gk), bk = op.bkoff(gk);
        uint32_t as = smu + (uint32_t)(st * 2 * 128 * RS) * 4u;
        uint32_t bs = as + (uint32_t)(128 * RS) * 4u;
        cp16(as + d0, aB + (ao0 < 0 ? 0 : ao0 + ak), ao0 >= 0);
        cp16(as + d1, aB + (ao1 < 0 ? 0 : ao1 + ak), ao1 >= 0);
        cp16(bs + d0, bB + (bo0 < 0 ? 0 : bo0 + bk), bo0 >= 0);
        cp16(bs + d1, bB + (bo1 < 0 ? 0 : bo1 + bk), bo1 >= 0);
        asm volatile("cp.async.commit_group;\n" ::: "memory");
    };

    auto COMPUTE = [&](int st) {
        const float* A = sm + st * 2 * 128 * RS;
        const float* B = A + 128 * RS;
#pragma unroll
        for (int ks = 0; ks < 16; ks += 8) {
            unsigned af[4][4], bf[4][2];
#pragma unroll
            for (int mt = 0; mt < 4; mt++) {
                const float* p = A + (wm + mt * 16 + r) * RS + ks + c;
                af[mt][0] = __float_as_uint(p[0]);
                af[mt][1] = __float_as_uint(p[8 * RS]);
                af[mt][2] = __float_as_uint(p[4]);
                af[mt][3] = __float_as_uint(p[8 * RS + 4]);
            }
#pragma unroll
            for (int nt = 0; nt < 4; nt++) {
                const float* p = B + (wn + nt * 8 + r) * RS + ks + c;
                bf[nt][0] = __float_as_uint(p[0]);
                bf[nt][1] = __float_as_uint(p[4]);
            }
#pragma unroll
            for (int mt = 0; mt < 4; mt++)
#pragma unroll
                for (int nt = 0; nt < 4; nt++) {
                    asm volatile(
                        "mma.sync.aligned.m16n8k8.row.col.f32.tf32.tf32.f32 "
                        "{%0,%1,%2,%3}, {%4,%5,%6,%7}, {%8,%9}, {%0,%1,%2,%3};\n"
                        : "+f"(acc[mt][nt][0]), "+f"(acc[mt][nt][1]),
                          "+f"(acc[mt][nt][2]), "+f"(acc[mt][nt][3])
                        : "r"(af[mt][0]), "r"(af[mt][1]), "r"(af[mt][2]), "r"(af[mt][3]),
                          "r"(bf[nt][0]), "r"(bf[nt][1]));
                }
        }
    };

    const int nkb = op.K / 16;
    FETCH(0, 0);
    for (int kb = 0; kb < nkb; kb++) {
        if (kb + 1 < nkb) {
            FETCH(kb + 1, (kb + 1) & 1);
            asm volatile("cp.async.wait_group 1;\n" ::: "memory");
        } else {
            asm volatile("cp.async.wait_group 0;\n" ::: "memory");
        }
        __syncthreads();
        COMPUTE(kb & 1);
        __syncthreads();
    }

    // epilogue
#pragma unroll
    for (int mt = 0; mt < 4; mt++) {
        int m0 = bm + wm + mt * 16 + r;
#pragma unroll
        for (int nt = 0; nt < 4; nt++) {
            int n0 = bn + wn + nt * 8 + 2 * c;
            if (m0 < op.M) {
                if (n0     < op.N) op.store(z, m0, n0,     acc[mt][nt][0]);
                if (n0 + 1 < op.N) op.store(z, m0, n0 + 1, acc[mt][nt][1]);
            }
            if (m0 + 8 < op.M) {
                if (n0     < op.N) op.store(z, m0 + 8, n0,     acc[mt][nt][2]);
                if (n0 + 1 < op.N) op.store(z, m0 + 8, n0 + 1, acc[mt][nt][3]);
            }
        }
    }
}

// ---------------- GEMM operand functors ----------------
struct OpQKV {
    const float* bias; const float* Wr;
    int sel; int M, N, K;
    __device__ __forceinline__ const float* abase(int) const { return g_xr; }
    __device__ __forceinline__ const float* bbase(int) const { return Wr; }
    __device__ __forceinline__ int arow(int, int m) const { return m * DM; }
    __device__ __forceinline__ int akoff(int k) const { return k; }
    __device__ __forceinline__ int brow(int, int n) const { return n * DM; }
    __device__ __forceinline__ int bkoff(int k) const { return k; }
    __device__ __forceinline__ void store(int, int m, int n, float v) const {
        int bb = m / LL, l = m % LL;
        int h = n >> 9, cc = n & 511;
        qkv_out_ptr(sel)[((bb * NHEAD + h) * LL + l) * HD + cc] = rnd32(v + bias[n]);
    }
};

struct OpPool {
    int selIn, selOut; int M, N, K;
    __device__ __forceinline__ const float* abase(int) const { return pool_in_ptr(selIn, g_xr); }
    __device__ __forceinline__ const float* bbase(int) const { return g_wp[selOut]; }
    __device__ __forceinline__ int arow(int z, int m) const {
        int t = m / 196, rem = m % 196;
        int hy = rem / 14, wx = rem % 14;
        int l00 = 1 + (t * HH + 2 * hy) * WWW + 2 * wx;
        return (z * LL + l00) * HD;
    }
    __device__ __forceinline__ int akoff(int k) const {
        int patch = k >> 9;
        return (k & 511) + ((patch >> 1) * WWW + (patch & 1)) * HD;
    }
    __device__ __forceinline__ int brow(int, int n) const { return n * 2048; }
    __device__ __forceinline__ int bkoff(int k) const { return k; }
    __device__ __forceinline__ void store(int z, int m, int n, float v) const {
        int idx = (z * LP + 1 + m) * HD + n;
        pool_out_ptr(selOut)[idx] = v;
        if (selOut == 0) g_PQr[idx] = rnd32(v);
    }
};

struct OpLogits {
    int M, N, K;
    __device__ __forceinline__ const float* abase(int) const { return g_PQr; }
    __device__ __forceinline__ const float* bbase(int) const { return g_Kmod; }
    __device__ __forceinline__ int arow(int z, int m) const { return (z * LP + m) * HD; }
    __device__ __forceinline__ int akoff(int k) const { return k; }
    __device__ __forceinline__ int brow(int z, int n) const { return (z * LP + n) * HD; }
    __device__ __forceinline__ int bkoff(int k) const { return k; }
    __device__ __forceinline__ void store(int z, int m, int n, float v) const {
        g_logits[(z * LP + m) * LPP + n] = v;
    }
};

struct OpAV {
    int M, N, K;
    __device__ __forceinline__ const float* abase(int) const { return g_logits; }
    __device__ __forceinline__ const float* bbase(int) const { return g_PVt; }
    __device__ __forceinline__ int arow(int z, int m) const { return (z * LP + m) * LPP; }
    __device__ __forceinline__ int akoff(int k) const { return k; }
    __device__ __forceinline__ int brow(int z, int n) const { return (z * HD + n) * LPP; }
    __device__ __forceinline__ int bkoff(int k) const { return k; }
    __device__ __forceinline__ void store(int z, int m, int n, float v) const {
        float pq = g_PQ[(z * LP + m) * HD + n];
        g_att[(z * LP + m) * HD + n] = rnd32(v + (m == 0 ? 1.f : 2.f) * pq);
    }
};

struct OpY {
    const float* bd;
    int M, N, K;
    __device__ __forceinline__ const float* abase(int) const { return g_att; }
    __device__ __forceinline__ const float* bbase(int) const { return g_Wdr; }
    __device__ __forceinline__ int arow(int, int m) const {
        int bb = m / LP, q = m % LP;
        return (bb * NHEAD * LP + q) * HD;
    }
    __device__ __forceinline__ int akoff(int k) const {
        return (k >> 9) * (LP * HD) + (k & 511);
    }
    __device__ __forceinline__ int brow(int, int n) const { return n * (NHEAD * HD); }
    __device__ __forceinline__ int bkoff(int k) const { return k; }
    __device__ __forceinline__ void store(int, int m, int n, float v) const {
        g_y[m * DM + n] = v + bd[n] + g_PX[m * DM + n];
    }
};

// ---------------- small kernels ----------------
__global__ void round_k(float* dst, const float* src, int n) {
    int i = blockIdx.x * 256 + threadIdx.x;
    if (i < n) dst[i] = rnd32(src[i]);
}

// pack pool weight: dst[n*2048 + patch*512 + ci] = rnd(src[n*2048 + ci*4 + patch])
__global__ void pack_k(float* dst, const float* src) {
    int i = blockIdx.x * 256 + threadIdx.x;
    if (i >= HD * 2048) return;
    int ci = i & 511, patch = (i >> 9) & 3, n = i >> 11;
    dst[n * 2048 + patch * 512 + ci] = rnd32(src[n * 2048 + ci * 4 + patch]);
}

__global__ void cls_copy_k(int sel, const float* x, int nimg) {
    int i = blockIdx.x * 256 + threadIdx.x;
    if (i >= nimg * HD) return;
    int z = i >> 9, cc = i & 511;
    float v = pool_in_ptr(sel, x)[z * LL * HD + cc];
    pool_out_ptr(sel)[z * LP * HD + cc] = v;
    if (sel == 0) g_PQr[z * LP * HD + cc] = rnd32(v);
}

__global__ void emb_k() {
    int i = blockIdx.x * 256 + threadIdx.x;
    if (i >= NP * HD) return;
    int tok = i >> 9, d = i & 511;
    int t = tok / 196, rem = tok % 196;
    int hy = rem / 14, wx = rem % 14;
    float pos; int j, half;
    if (d < 170)      { pos = (float)t;  j = d;        half = 85; }
    else if (d < 340) { pos = (float)hy; j = d - 170;  half = 85; }
    else              { pos = (float)wx; j = d - 340;  half = 86; }
    bool is_cos = (j >= half);
    int jj = is_cos ? j - half : j;
    float omega = powf(10000.f, -(float)jj / (float)half);
    float ang = pos * omega;
    g_emb[i] = is_cos ? cosf(ang) : sinf(ang);
}

__global__ void kmod_k() {
    int i = blockIdx.x * 256 + threadIdx.x;
    if (i >= BHN * LP * HD) return;
    int cc = i & 511;
    int kpos = (i >> 9) % LP;
    float v = g_PK[i] * ATT_SCALE;
    if (kpos >= 1) v += g_emb[(kpos - 1) * HD + cc];
    g_Kmod[i] = rnd32(v);
}

__global__ void row0_k() {
    int w = (blockIdx.x * blockDim.x + threadIdx.x) >> 5;
    int lane = threadIdx.x & 31;
    if (w >= BHN * LP) return;
    int z = w / LP, n = w % LP;
    const float* q = g_PQ + z * LP * HD;
    const float* kk = g_PK + (z * LP + n) * HD;
    float s = 0.f;
    for (int i = lane; i < HD; i += 32) s += q[i] * kk[i];
#pragma unroll
    for (int o = 16; o; o >>= 1) s += __shfl_xor_sync(0xffffffffu, s, o);
    if (lane == 0) g_logits[(long long)z * LP * LPP + n] = s * ATT_SCALE;
}

__global__ void softmax_k() {
    int row = blockIdx.x;                 // BHN*LP rows
    float* p = g_logits + (long long)row * LPP;
    int tid = threadIdx.x;
    float v[7];
    float m = -1e30f;
#pragma unroll
    for (int i = 0; i < 7; i++) {
        int idx = tid + i * 256;
        v[i] = (idx < LP) ? p[idx] : -1e30f;
        m = fmaxf(m, v[i]);
    }
    __shared__ float red[256];
    red[tid] = m; __syncthreads();
    for (int s = 128; s > 0; s >>= 1) {
        if (tid < s) red[tid] = fmaxf(red[tid], red[tid + s]);
        __syncthreads();
    }
    m = red[0]; __syncthreads();
    float sum = 0.f;
#pragma unroll
    for (int i = 0; i < 7; i++) {
        int idx = tid + i * 256;
        v[i] = (idx < LP) ? expf(v[i] - m) : 0.f;
        sum += v[i];
    }
    red[tid] = sum; __syncthreads();
    for (int s = 128; s > 0; s >>= 1) {
        if (tid < s) red[tid] += red[tid + s];
        __syncthreads();
    }
    float inv = 1.f / red[0];
#pragma unroll
    for (int i = 0; i < 7; i++) {
        int idx = tid + i * 256;
        if (idx < LP) p[idx] = rnd32(v[i] * inv);
    }
    if (tid < LPP - LP) p[LP + tid] = 0.f;   // zero k-pad
}

__global__ void transpose_pv_k() {
    int i = blockIdx.x * 256 + threadIdx.x;
    if (i >= BHN * HD * LPP) return;
    int k = i % LPP;
    int rest = i / LPP;
    int cc = rest & 511;
    int z = rest >> 9;
    g_PVt[i] = (k < LP) ? rnd32(g_PV[(z * LP + k) * HD + cc]) : 0.f;
}

__global__ void ln_k(const float* gamma, const float* beta, float* out) {
    int row = blockIdx.x;
    const float* p = g_y + row * DM;
    int tid = threadIdx.x;
    float v[4];
#pragma unroll
    for (int i = 0; i < 4; i++) v[i] = p[tid + i * 128];
    __shared__ float red[128];
    float s = v[0] + v[1] + v[2] + v[3];
    red[tid] = s; __syncthreads();
    for (int st = 64; st > 0; st >>= 1) {
        if (tid < st) red[tid] += red[tid + st];
        __syncthreads();
    }
    float mu = red[0] / (float)DM;
    __syncthreads();
    float sq = 0.f;
#pragma unroll
    for (int i = 0; i < 4; i++) { float d = v[i] - mu; sq += d * d; }
    red[tid] = sq; __syncthreads();
    for (int st = 64; st > 0; st >>= 1) {
        if (tid < st) red[tid] += red[tid + st];
        __syncthreads();
    }
    float inv = rsqrtf(red[0] / (float)DM + 1e-5f);
    __syncthreads();
#pragma unroll
    for (int i = 0; i < 4; i++) {
        int cc = tid + i * 128;
        out[row * DM + cc] = (v[i] - mu) * inv * gamma[cc] + beta[cc];
    }
}

// ---------------- launch ----------------
extern "C" void kernel_launch(void* const* d_in, const int* in_sizes, int n_in,
                              void* d_out, int out_size) {
    const float* x    = (const float*)d_in[0];
    const float* Wq   = (const float*)d_in[1];
    const float* bq   = (const float*)d_in[2];
    const float* Wk   = (const float*)d_in[3];
    const float* bk   = (const float*)d_in[4];
    const float* Wv   = (const float*)d_in[5];
    const float* bv   = (const float*)d_in[6];
    const float* wpq  = (const float*)d_in[7];
    const float* wpk  = (const float*)d_in[8];
    const float* wpv  = (const float*)d_in[9];
    const float* wpx  = (const float*)d_in[10];
    const float* Wd   = (const float*)d_in[11];
    const float* bd   = (const float*)d_in[12];
    const float* gamma= (const float*)d_in[13];
    const float* beta = (const float*)d_in[14];
    float* out = (float*)d_out;

    // symbol addresses for rounding targets
    float *p_xr, *p_Wqr, *p_Wkr, *p_Wvr, *p_Wdr, *p_wp;
    cudaGetSymbolAddress((void**)&p_xr,  g_xr);
    cudaGetSymbolAddress((void**)&p_Wqr, g_Wqr);
    cudaGetSymbolAddress((void**)&p_Wkr, g_Wkr);
    cudaGetSymbolAddress((void**)&p_Wvr, g_Wvr);
    cudaGetSymbolAddress((void**)&p_Wdr, g_Wdr);
    cudaGetSymbolAddress((void**)&p_wp,  g_wp);

    // 0) pre-round / pack all GEMM operands
    int nx = BATCH * LL * DM;
    round_k<<<(nx + 255) / 256, 256>>>(p_xr, x, nx);
    int nw = NHEAD * HD * DM;
    round_k<<<(nw + 255) / 256, 256>>>(p_Wqr, Wq, nw);
    round_k<<<(nw + 255) / 256, 256>>>(p_Wkr, Wk, nw);
    round_k<<<(nw + 255) / 256, 256>>>(p_Wvr, Wv, nw);
    round_k<<<(nw + 255) / 256, 256>>>(p_Wdr, Wd, nw);
    int npk = HD * 2048;
    pack_k<<<(npk + 255) / 256, 256>>>(p_wp + 0 * npk, wpq);
    pack_k<<<(npk + 255) / 256, 256>>>(p_wp + 1 * npk, wpk);
    pack_k<<<(npk + 255) / 256, 256>>>(p_wp + 2 * npk, wpv);
    pack_k<<<(npk + 255) / 256, 256>>>(p_wp + 3 * npk, wpx);

    // 1) QKV projections
    {
        OpQKV op; op.M = BATCH * LL; op.N = NHEAD * HD; op.K = DM;
        dim3 g((op.N + 127) / 128, (op.M + 127) / 128, 1);
        op.Wr = p_Wqr; op.bias = bq; op.sel = 0; gemm_tc<<<g, 256>>>(op);
        op.Wr = p_Wkr; op.bias = bk; op.sel = 1; gemm_tc<<<g, 256>>>(op);
        op.Wr = p_Wvr; op.bias = bv; op.sel = 2; gemm_tc<<<g, 256>>>(op);
    }
    // 2) pooling convs (im2col GEMM) + cls passthrough
    {
        OpPool op; op.M = NP; op.N = HD; op.K = 2048;
        dim3 g(4, (NP + 127) / 128, BHN);
        op.selIn = 0; op.selOut = 0; gemm_tc<<<g, 256>>>(op);
        op.selIn = 1; op.selOut = 1; gemm_tc<<<g, 256>>>(op);
        op.selIn = 2; op.selOut = 2; gemm_tc<<<g, 256>>>(op);
        dim3 gx(4, (NP + 127) / 128, BATCH);
        op.selIn = 3; op.selOut = 3; gemm_tc<<<gx, 256>>>(op);
    }
    cls_copy_k<<<(BHN * HD + 255) / 256, 256>>>(0, p_xr, BHN);
    cls_copy_k<<<(BHN * HD + 255) / 256, 256>>>(1, p_xr, BHN);
    cls_copy_k<<<(BHN * HD + 255) / 256, 256>>>(2, p_xr, BHN);
    cls_copy_k<<<(BATCH * HD + 255) / 256, 256>>>(3, p_xr, BATCH);

    // 3) positional embedding + Kmod
    emb_k<<<(NP * HD + 255) / 256, 256>>>();
    kmod_k<<<(BHN * LP * HD + 255) / 256, 256>>>();

    // 4) logits GEMM, row-0 repair, softmax
    {
        OpLogits op; op.M = LP; op.N = LP; op.K = HD;
        dim3 g((LP + 127) / 128, (LP + 127) / 128, BHN);
        gemm_tc<<<g, 256>>>(op);
    }
    row0_k<<<(BHN * LP * 32 + 255) / 256, 256>>>();
    softmax_k<<<BHN * LP, 256>>>();

    // 5) attn @ PV (+residual)
    transpose_pv_k<<<(BHN * HD * LPP + 255) / 256, 256>>>();
    {
        OpAV op; op.M = LP; op.N = HD; op.K = LPP;
        dim3 g((HD + 127) / 128, (LP + 127) / 128, BHN);
        gemm_tc<<<g, 256>>>(op);
    }

    // 6) output projection + bias + PX, then LayerNorm
    {
        OpY op; op.bd = bd; op.M = BATCH * LP; op.N = DM; op.K = NHEAD * HD;
        dim3 g((DM + 127) / 128, (op.M + 127) / 128, 1);
        gemm_tc<<<g, 256>>>(op);
    }
    ln_k<<<BATCH * LP, 128>>>(gamma, beta, out);
}

// round 7
// speedup vs baseline: 5.5941x; 1.4150x over previous
#include <cuda_runtime.h>
#include <math.h>
#include <stdint.h>

#define BATCH 2
#define NHEAD 8
#define DM 512
#define HD 512
#define TT 8
#define HH 28
#define WWW 28
#define LL 6273          // 1 + 8*28*28
#define LP 1569          // 1 + 8*14*14
#define LPP 1600         // padded K for attention GEMMs
#define NP 1568
#define BHN 16           // BATCH*NHEAD
#define ATT_SCALE 0.04419417382415922f   // 1/sqrt(512)

// ---------------- scratch (static device allocations) ----------------
__device__ __align__(256) float g_xr  [BATCH * LL * DM];       // rounded x
__device__ __align__(256) float g_Wdr [DM * NHEAD * HD];       // rounded Wd
__device__ __align__(256) float g_wp  [4][HD * 2048];          // packed+rounded pool weights [n][p*512+ci]
__device__ __align__(256) float g_WqT [3][DM * NHEAD * HD];    // rounded W^T: [d][h*512+ci]
__device__ __align__(256) float g_Weff[3 * NHEAD * HD * 2048]; // [s][h][co][p*512+d], rounded
__device__ __align__(256) float g_be  [3][NHEAD * HD];         // pooled bias
__device__ __align__(256) float g_PQ  [BHN * LP * HD];         // raw
__device__ __align__(256) float g_PQr [BHN * LP * HD];         // rounded
__device__ __align__(256) float g_PK  [BHN * LP * HD];         // raw (row0)
__device__ __align__(256) float g_PVt [BHN * HD * LPP];        // rounded, k-padded (pad stays 0)
__device__ __align__(256) float g_Kmod[BHN * LP * HD];         // rounded scale*PK+emb
__device__ __align__(256) float g_logits[BHN * LP * LPP];      // stride LPP
__device__ __align__(256) float g_att [BHN * LP * HD];         // rounded (+residual)
__device__ __align__(256) float g_PX  [BATCH * LP * HD];       // raw
__device__ __align__(256) float g_emb [NP * HD];
__device__ __align__(256) float g_y   [BATCH * LP * HD];

__device__ __forceinline__ float rnd32(float v) {
    unsigned u;
    asm("cvt.rna.tf32.f32 %0, %1;" : "=r"(u) : "f"(v));
    return __uint_as_float(u);
}

__device__ __forceinline__ void cp16(uint32_t dst, const float* src, bool valid) {
    if (valid)
        asm volatile("cp.async.cg.shared.global [%0], [%1], 16;\n" :: "r"(dst), "l"(src));
    else
        asm volatile("cp.async.cg.shared.global [%0], [%1], 16, %2;\n" :: "r"(dst), "l"(src), "r"(0));
}

// ---------------- tf32 tensor-core GEMM: 128x128x16 tiles, cp.async double-buffered ----------------
#define RS 20
template <class OP>
__global__ void __launch_bounds__(256, 2) gemm_tc(OP op) {
    __shared__ float sm[4 * 128 * RS];
    __shared__ int aT[128], bT[128];

    const int z  = blockIdx.z;
    const int bm = blockIdx.y * 128;
    const int bn = blockIdx.x * 128;
    const int tid = threadIdx.x, lane = tid & 31;
    const int wid = tid >> 5;
    const int wm = (wid >> 2) * 64, wn = (wid & 3) * 32;
    const int r = lane >> 2, c = lane & 3;

    if (tid < 128) { int gm = bm + tid; aT[tid] = (gm < op.M) ? op.arow(z, gm) : -1; }
    else           { int gn = bn + tid - 128; bT[tid - 128] = (gn < op.N) ? op.brow(z, gn) : -1; }
    __syncthreads();

    const float* aB = op.abase(z);
    const float* bB = op.bbase(z);

    const int kq = tid & 3;
    const int mr = tid >> 2;
    const int ao0 = aT[mr], ao1 = aT[mr + 64];
    const int bo0 = bT[mr], bo1 = bT[mr + 64];

    const uint32_t smu = (uint32_t)__cvta_generic_to_shared(sm);
    const uint32_t d0 = (uint32_t)(mr * RS + kq * 4) * 4u;
    const uint32_t d1 = (uint32_t)((mr + 64) * RS + kq * 4) * 4u;

    float acc[4][4][4];
#pragma unroll
    for (int i = 0; i < 4; i++)
#pragma unroll
        for (int j = 0; j < 4; j++)
#pragma unroll
            for (int e = 0; e < 4; e++) acc[i][j][e] = 0.f;

    auto FETCH = [&](int kb, int st) {
        int gk = kb * 16 + kq * 4;
        int ak = op.akoff(gk), bk = op.bkoff(gk);
        uint32_t as = smu + (uint32_t)(st * 2 * 128 * RS) * 4u;
        uint32_t bs = as + (uint32_t)(128 * RS) * 4u;
        cp16(as + d0, aB + (ao0 < 0 ? 0 : ao0 + ak), ao0 >= 0);
        cp16(as + d1, aB + (ao1 < 0 ? 0 : ao1 + ak), ao1 >= 0);
        cp16(bs + d0, bB + (bo0 < 0 ? 0 : bo0 + bk), bo0 >= 0);
        cp16(bs + d1, bB + (bo1 < 0 ? 0 : bo1 + bk), bo1 >= 0);
        asm volatile("cp.async.commit_group;\n" ::: "memory");
    };

    auto COMPUTE = [&](int st) {
        const float* A = sm + st * 2 * 128 * RS;
        const float* B = A + 128 * RS;
#pragma unroll
        for (int ks = 0; ks < 16; ks += 8) {
            unsigned af[4][4], bf[4][2];
#pragma unroll
            for (int mt = 0; mt < 4; mt++) {
                const float* p = A + (wm + mt * 16 + r) * RS + ks + c;
                af[mt][0] = __float_as_uint(p[0]);
                af[mt][1] = __float_as_uint(p[8 * RS]);
                af[mt][2] = __float_as_uint(p[4]);
                af[mt][3] = __float_as_uint(p[8 * RS + 4]);
            }
#pragma unroll
            for (int nt = 0; nt < 4; nt++) {
                const float* p = B + (wn + nt * 8 + r) * RS + ks + c;
                bf[nt][0] = __float_as_uint(p[0]);
                bf[nt][1] = __float_as_uint(p[4]);
            }
#pragma unroll
            for (int mt = 0; mt < 4; mt++)
#pragma unroll
                for (int nt = 0; nt < 4; nt++) {
                    asm volatile(
                        "mma.sync.aligned.m16n8k8.row.col.f32.tf32.tf32.f32 "
                        "{%0,%1,%2,%3}, {%4,%5,%6,%7}, {%8,%9}, {%0,%1,%2,%3};\n"
                        : "+f"(acc[mt][nt][0]), "+f"(acc[mt][nt][1]),
                          "+f"(acc[mt][nt][2]), "+f"(acc[mt][nt][3])
                        : "r"(af[mt][0]), "r"(af[mt][1]), "r"(af[mt][2]), "r"(af[mt][3]),
                          "r"(bf[nt][0]), "r"(bf[nt][1]));
                }
        }
    };

    const int nkb = op.K / 16;
    FETCH(0, 0);
    for (int kb = 0; kb < nkb; kb++) {
        if (kb + 1 < nkb) {
            FETCH(kb + 1, (kb + 1) & 1);
            asm volatile("cp.async.wait_group 1;\n" ::: "memory");
        } else {
            asm volatile("cp.async.wait_group 0;\n" ::: "memory");
        }
        __syncthreads();
        COMPUTE(kb & 1);
        __syncthreads();
    }

#pragma unroll
    for (int mt = 0; mt < 4; mt++) {
        int m0 = bm + wm + mt * 16 + r;
#pragma unroll
        for (int nt = 0; nt < 4; nt++) {
            int n0 = bn + wn + nt * 8 + 2 * c;
            if (m0 < op.M) {
                if (n0     < op.N) op.store(z, m0, n0,     acc[mt][nt][0]);
                if (n0 + 1 < op.N) op.store(z, m0, n0 + 1, acc[mt][nt][1]);
            }
            if (m0 + 8 < op.M) {
                if (n0     < op.N) op.store(z, m0 + 8, n0,     acc[mt][nt][2]);
                if (n0 + 1 < op.N) op.store(z, m0 + 8, n0 + 1, acc[mt][nt][3]);
            }
        }
    }
}

// ---------------- functors ----------------
// Weff[s,h,p][co,d] = sum_ci wp_s[co,ci,p] * W_s[h*512+ci, d];  z = s*32 + h*4 + p
struct OpWeff {
    const float* WqT0;   // g_WqT base
    int M, N, K;
    __device__ __forceinline__ const float* abase(int z) const {
        return g_wp[z >> 5];
    }
    __device__ __forceinline__ const float* bbase(int z) const {
        return WqT0 + (z >> 5) * (DM * NHEAD * HD);
    }
    __device__ __forceinline__ int arow(int z, int m) const {
        return m * 2048 + (z & 3) * 512;
    }
    __device__ __forceinline__ int akoff(int k) const { return k; }
    __device__ __forceinline__ int brow(int z, int n) const {
        return n * (NHEAD * HD) + ((z >> 2) & 7) * 512;
    }
    __device__ __forceinline__ int bkoff(int k) const { return k; }
    __device__ __forceinline__ void store(int z, int m, int n, float v) const {
        int s = z >> 5, h = (z >> 2) & 7, p = z & 3;
        g_Weff[(((s * NHEAD + h) * HD) + m) * 2048 + p * 512 + n] = rnd32(v);
    }
};

// pooled projection: z=(b,h); a = im2col(x), b = Weff[s,h]; K=2048
struct OpPoolP {
    int sel;             // 0=Q,1=K,2=V
    int M, N, K;
    __device__ __forceinline__ const float* abase(int) const { return g_xr; }
    __device__ __forceinline__ const float* bbase(int z) const {
        return g_Weff + (sel * NHEAD + (z & 7)) * (HD * 2048);
    }
    __device__ __forceinline__ int arow(int z, int m) const {
        int t = m / 196, rem = m % 196;
        int hy = rem / 14, wx = rem % 14;
        int l00 = 1 + (t * HH + 2 * hy) * WWW + 2 * wx;
        return ((z >> 3) * LL + l00) * DM;
    }
    __device__ __forceinline__ int akoff(int k) const {
        int p = k >> 9;
        return (k & 511) + ((p >> 1) * WWW + (p & 1)) * DM;
    }
    __device__ __forceinline__ int brow(int, int n) const { return n * 2048; }
    __device__ __forceinline__ int bkoff(int k) const { return k; }
    __device__ __forceinline__ void store(int z, int m, int n, float v) const {
        v += g_be[sel][(z & 7) * 512 + n];
        if (sel == 0) {
            int idx = (z * LP + 1 + m) * HD + n;
            g_PQ[idx] = v;
            g_PQr[idx] = rnd32(v);
        } else if (sel == 1) {
            int idx = (z * LP + 1 + m) * HD + n;
            g_PK[idx] = v;
            g_Kmod[idx] = rnd32(ATT_SCALE * v + g_emb[m * HD + n]);
        } else {
            g_PVt[(z * HD + n) * LPP + 1 + m] = rnd32(v);
        }
    }
};

// x pooling: z = b; a = im2col(x), b = g_wp[3]
struct OpPoolX {
    int M, N, K;
    __device__ __forceinline__ const float* abase(int) const { return g_xr; }
    __device__ __forceinline__ const float* bbase(int) const { return g_wp[3]; }
    __device__ __forceinline__ int arow(int z, int m) const {
        int t = m / 196, rem = m % 196;
        int hy = rem / 14, wx = rem % 14;
        int l00 = 1 + (t * HH + 2 * hy) * WWW + 2 * wx;
        return (z * LL + l00) * DM;
    }
    __device__ __forceinline__ int akoff(int k) const {
        int p = k >> 9;
        return (k & 511) + ((p >> 1) * WWW + (p & 1)) * DM;
    }
    __device__ __forceinline__ int brow(int, int n) const { return n * 2048; }
    __device__ __forceinline__ int bkoff(int k) const { return k; }
    __device__ __forceinline__ void store(int z, int m, int n, float v) const {
        g_PX[(z * LP + 1 + m) * HD + n] = v;
    }
};

struct OpLogits {
    int M, N, K;
    __device__ __forceinline__ const float* abase(int) const { return g_PQr; }
    __device__ __forceinline__ const float* bbase(int) const { return g_Kmod; }
    __device__ __forceinline__ int arow(int z, int m) const { return (z * LP + m) * HD; }
    __device__ __forceinline__ int akoff(int k) const { return k; }
    __device__ __forceinline__ int brow(int z, int n) const { return (z * LP + n) * HD; }
    __device__ __forceinline__ int bkoff(int k) const { return k; }
    __device__ __forceinline__ void store(int z, int m, int n, float v) const {
        g_logits[(z * LP + m) * LPP + n] = v;
    }
};

struct OpAV {
    int M, N, K;
    __device__ __forceinline__ const float* abase(int) const { return g_logits; }
    __device__ __forceinline__ const float* bbase(int) const { return g_PVt; }
    __device__ __forceinline__ int arow(int z, int m) const { return (z * LP + m) * LPP; }
    __device__ __forceinline__ int akoff(int k) const { return k; }
    __device__ __forceinline__ int brow(int z, int n) const { return (z * HD + n) * LPP; }
    __device__ __forceinline__ int bkoff(int k) const { return k; }
    __device__ __forceinline__ void store(int z, int m, int n, float v) const {
        float pq = g_PQ[(z * LP + m) * HD + n];
        g_att[(z * LP + m) * HD + n] = rnd32(v + (m == 0 ? 1.f : 2.f) * pq);
    }
};

struct OpY {
    const float* bd;
    int M, N, K;
    __device__ __forceinline__ const float* abase(int) const { return g_att; }
    __device__ __forceinline__ const float* bbase(int) const { return g_Wdr; }
    __device__ __forceinline__ int arow(int, int m) const {
        int bb = m / LP, q = m % LP;
        return (bb * NHEAD * LP + q) * HD;
    }
    __device__ __forceinline__ int akoff(int k) const {
        return (k >> 9) * (LP * HD) + (k & 511);
    }
    __device__ __forceinline__ int brow(int, int n) const { return n * (NHEAD * HD); }
    __device__ __forceinline__ int bkoff(int k) const { return k; }
    __device__ __forceinline__ void store(int, int m, int n, float v) const {
        g_y[m * DM + n] = v + bd[n] + g_PX[m * DM + n];
    }
};

// ---------------- small kernels ----------------
__global__ void round_k(float* dst, const float* src, int n) {
    int i = blockIdx.x * 256 + threadIdx.x;
    if (i < n) dst[i] = rnd32(src[i]);
}

__global__ void pack_k(float* dst, const float* src) {
    int i = blockIdx.x * 256 + threadIdx.x;
    if (i >= HD * 2048) return;
    int ci = i & 511, patch = (i >> 9) & 3, n = i >> 11;
    dst[n * 2048 + patch * 512 + ci] = rnd32(src[n * 2048 + ci * 4 + patch]);
}

// W [4096, 512] -> WqT [512, 4096] (rounded); grid (16, 128, 3), block (32,8)
__global__ void transW_k(const float* Wq, const float* Wk, const float* Wv) {
    __shared__ float t[32][33];
    int zz = blockIdx.z;
    const float* src = zz == 0 ? Wq : (zz == 1 ? Wk : Wv);
    float* dst = &g_WqT[zz][0];
    int bx = blockIdx.x * 32;     // d
    int by = blockIdx.y * 32;     // row (h*512+ci)
    int tx = threadIdx.x, ty = threadIdx.y;
#pragma unroll
    for (int i = 0; i < 4; i++)
        t[ty + i * 8][tx] = src[(by + ty + i * 8) * DM + bx + tx];
    __syncthreads();
#pragma unroll
    for (int i = 0; i < 4; i++)
        dst[(bx + ty + i * 8) * (NHEAD * HD) + by + tx] = rnd32(t[tx][ty + i * 8]);
}

// pooled bias: be[s][h*512+co] = sum_ci (sum_p wp_s[co,ci,p]) * b_s[h*512+ci]
__global__ void biaseff_k(const float* wpq, const float* wpk, const float* wpv,
                          const float* bq, const float* bk, const float* bv) {
    int s = blockIdx.y;
    const float* w = s == 0 ? wpq : (s == 1 ? wpk : wpv);
    const float* b = s == 0 ? bq : (s == 1 ? bk : bv);
    int gw = blockIdx.x * 8 + (threadIdx.x >> 5);      // 0..4095 = h*512+co
    int lane = threadIdx.x & 31;
    int h = gw >> 9, co = gw & 511;
    float sum = 0.f;
    for (int ci = lane; ci < 512; ci += 32) {
        const float* wp4 = w + co * 2048 + ci * 4;
        sum += (wp4[0] + wp4[1] + wp4[2] + wp4[3]) * b[h * 512 + ci];
    }
#pragma unroll
    for (int o = 16; o; o >>= 1) sum += __shfl_xor_sync(0xffffffffu, sum, o);
    if (lane == 0) g_be[s][gw] = sum;
}

// cls-token projections; grid (1024, 3), block 256 (8 warps): warp per (z,c)
__global__ void clsproj_k(const float* x,
                          const float* Wq, const float* Wk, const float* Wv,
                          const float* bq, const float* bk, const float* bv) {
    int s = blockIdx.y;
    const float* W = s == 0 ? Wq : (s == 1 ? Wk : Wv);
    const float* bb = s == 0 ? bq : (s == 1 ? bk : bv);
    int gw = blockIdx.x * 8 + (threadIdx.x >> 5);      // 0..8191 = z*512+c
    int lane = threadIdx.x & 31;
    int z = gw >> 9, c = gw & 511;
    int b = z >> 3, h = z & 7;
    const float* xr = x + (long long)b * LL * DM;
    const float* wr = W + (h * 512 + c) * DM;
    float sum = 0.f;
    for (int d = lane; d < DM; d += 32) sum += xr[d] * wr[d];
#pragma unroll
    for (int o = 16; o; o >>= 1) sum += __shfl_xor_sync(0xffffffffu, sum, o);
    if (lane == 0) {
        float v = sum + bb[h * 512 + c];
        if (s == 0) {
            g_PQ[z * LP * HD + c] = v;
            g_PQr[z * LP * HD + c] = rnd32(v);
        } else if (s == 1) {
            g_PK[z * LP * HD + c] = v;
            g_Kmod[z * LP * HD + c] = rnd32(ATT_SCALE * v);
        } else {
            g_PVt[(z * HD + c) * LPP] = rnd32(v);
        }
    }
}

__global__ void clsx_k(const float* x) {
    int i = blockIdx.x * 256 + threadIdx.x;
    if (i >= BATCH * DM) return;
    int z = i >> 9, c = i & 511;
    g_PX[z * LP * HD + c] = x[(long long)z * LL * DM + c];
}

__global__ void emb_k() {
    int i = blockIdx.x * 256 + threadIdx.x;
    if (i >= NP * HD) return;
    int tok = i >> 9, d = i & 511;
    int t = tok / 196, rem = tok % 196;
    int hy = rem / 14, wx = rem % 14;
    float pos; int j, half;
    if (d < 170)      { pos = (float)t;  j = d;        half = 85; }
    else if (d < 340) { pos = (float)hy; j = d - 170;  half = 85; }
    else              { pos = (float)wx; j = d - 340;  half = 86; }
    bool is_cos = (j >= half);
    int jj = is_cos ? j - half : j;
    float omega = powf(10000.f, -(float)jj / (float)half);
    float ang = pos * omega;
    g_emb[i] = is_cos ? cosf(ang) : sinf(ang);
}

__global__ void row0_k() {
    int w = (blockIdx.x * blockDim.x + threadIdx.x) >> 5;
    int lane = threadIdx.x & 31;
    if (w >= BHN * LP) return;
    int z = w / LP, n = w % LP;
    const float* q = g_PQ + z * LP * HD;
    const float* kk = g_PK + (z * LP + n) * HD;
    float s = 0.f;
    for (int i = lane; i < HD; i += 32) s += q[i] * kk[i];
#pragma unroll
    for (int o = 16; o; o >>= 1) s += __shfl_xor_sync(0xffffffffu, s, o);
    if (lane == 0) g_logits[(long long)z * LP * LPP + n] = s * ATT_SCALE;
}

__global__ void softmax_k() {
    int row = blockIdx.x;
    float* p = g_logits + (long long)row * LPP;
    int tid = threadIdx.x;
    float v[7];
    float m = -1e30f;
#pragma unroll
    for (int i = 0; i < 7; i++) {
        int idx = tid + i * 256;
        v[i] = (idx < LP) ? p[idx] : -1e30f;
        m = fmaxf(m, v[i]);
    }
    __shared__ float red[256];
    red[tid] = m; __syncthreads();
    for (int s = 128; s > 0; s >>= 1) {
        if (tid < s) red[tid] = fmaxf(red[tid], red[tid + s]);
        __syncthreads();
    }
    m = red[0]; __syncthreads();
    float sum = 0.f;
#pragma unroll
    for (int i = 0; i < 7; i++) {
        int idx = tid + i * 256;
        v[i] = (idx < LP) ? expf(v[i] - m) : 0.f;
        sum += v[i];
    }
    red[tid] = sum; __syncthreads();
    for (int s = 128; s > 0; s >>= 1) {
        if (tid < s) red[tid] += red[tid + s];
        __syncthreads();
    }
    float inv = 1.f / red[0];
#pragma unroll
    for (int i = 0; i < 7; i++) {
        int idx = tid + i * 256;
        if (idx < LP) p[idx] = rnd32(v[i] * inv);
    }
    if (tid < LPP - LP) p[LP + tid] = 0.f;
}

__global__ void ln_k(const float* gamma, const float* beta, float* out) {
    int row = blockIdx.x;
    const float* p = g_y + row * DM;
    int tid = threadIdx.x;
    float v[4];
#pragma unroll
    for (int i = 0; i < 4; i++) v[i] = p[tid + i * 128];
    __shared__ float red[128];
    float s = v[0] + v[1] + v[2] + v[3];
    red[tid] = s; __syncthreads();
    for (int st = 64; st > 0; st >>= 1) {
        if (tid < st) red[tid] += red[tid + st];
        __syncthreads();
    }
    float mu = red[0] / (float)DM;
    __syncthreads();
    float sq = 0.f;
#pragma unroll
    for (int i = 0; i < 4; i++) { float d = v[i] - mu; sq += d * d; }
    red[tid] = sq; __syncthreads();
    for (int st = 64; st > 0; st >>= 1) {
        if (tid < st) red[tid] += red[tid + st];
        __syncthreads();
    }
    float inv = rsqrtf(red[0] / (float)DM + 1e-5f);
    __syncthreads();
#pragma unroll
    for (int i = 0; i < 4; i++) {
        int cc = tid + i * 128;
        out[row * DM + cc] = (v[i] - mu) * inv * gamma[cc] + beta[cc];
    }
}

// ---------------- launch ----------------
extern "C" void kernel_launch(void* const* d_in, const int* in_sizes, int n_in,
                              void* d_out, int out_size) {
    const float* x    = (const float*)d_in[0];
    const float* Wq   = (const float*)d_in[1];
    const float* bq   = (const float*)d_in[2];
    const float* Wk   = (const float*)d_in[3];
    const float* bk   = (const float*)d_in[4];
    const float* Wv   = (const float*)d_in[5];
    const float* bv   = (const float*)d_in[6];
    const float* wpq  = (const float*)d_in[7];
    const float* wpk  = (const float*)d_in[8];
    const float* wpv  = (const float*)d_in[9];
    const float* wpx  = (const float*)d_in[10];
    const float* Wd   = (const float*)d_in[11];
    const float* bd   = (const float*)d_in[12];
    const float* gamma= (const float*)d_in[13];
    const float* beta = (const float*)d_in[14];
    float* out = (float*)d_out;

    float *p_xr, *p_Wdr, *p_wp, *p_WqT;
    cudaGetSymbolAddress((void**)&p_xr,  g_xr);
    cudaGetSymbolAddress((void**)&p_Wdr, g_Wdr);
    cudaGetSymbolAddress((void**)&p_wp,  g_wp);
    cudaGetSymbolAddress((void**)&p_WqT, g_WqT);

    // 0) prep: round x/Wd, pack pool weights, transpose+round W_{q,k,v}, emb, pooled bias
    int nx = BATCH * LL * DM;
    round_k<<<(nx + 255) / 256, 256>>>(p_xr, x, nx);
    int nw = NHEAD * HD * DM;
    round_k<<<(nw + 255) / 256, 256>>>(p_Wdr, Wd, nw);
    int npk = HD * 2048;
    pack_k<<<(npk + 255) / 256, 256>>>(p_wp + 0 * npk, wpq);
    pack_k<<<(npk + 255) / 256, 256>>>(p_wp + 1 * npk, wpk);
    pack_k<<<(npk + 255) / 256, 256>>>(p_wp + 2 * npk, wpv);
    pack_k<<<(npk + 255) / 256, 256>>>(p_wp + 3 * npk, wpx);
    transW_k<<<dim3(16, 128, 3), dim3(32, 8)>>>(Wq, Wk, Wv);
    emb_k<<<(NP * HD + 255) / 256, 256>>>();
    biaseff_k<<<dim3(512, 3), 256>>>(wpq, wpk, wpv, bq, bk, bv);

    // 1) Weff = wpool @ W  (96 x 512^3)
    {
        OpWeff op; op.WqT0 = p_WqT; op.M = 512; op.N = 512; op.K = 512;
        gemm_tc<<<dim3(4, 4, 96), 256>>>(op);
    }

    // 2) fused pooled projections + x-pool + cls
    {
        OpPoolP op; op.M = NP; op.N = HD; op.K = 2048;
        dim3 g(4, (NP + 127) / 128, BHN);
        op.sel = 0; gemm_tc<<<g, 256>>>(op);
        op.sel = 1; gemm_tc<<<g, 256>>>(op);
        op.sel = 2; gemm_tc<<<g, 256>>>(op);
    }
    {
        OpPoolX op; op.M = NP; op.N = HD; op.K = 2048;
        gemm_tc<<<dim3(4, (NP + 127) / 128, BATCH), 256>>>(op);
    }
    clsproj_k<<<dim3(1024, 3), 256>>>(x, Wq, Wk, Wv, bq, bk, bv);
    clsx_k<<<(BATCH * DM + 255) / 256, 256>>>(x);

    // 3) logits GEMM, row-0 repair, softmax
    {
        OpLogits op; op.M = LP; op.N = LP; op.K = HD;
        gemm_tc<<<dim3((LP + 127) / 128, (LP + 127) / 128, BHN), 256>>>(op);
    }
    row0_k<<<(BHN * LP * 32 + 255) / 256, 256>>>();
    softmax_k<<<BHN * LP, 256>>>();

    // 4) attn @ PV (+residual)
    {
        OpAV op; op.M = LP; op.N = HD; op.K = LPP;
        gemm_tc<<<dim3((HD + 127) / 128, (LP + 127) / 128, BHN), 256>>>(op);
    }

    // 5) output projection + bias + PX, then LayerNorm
    {
        OpY op; op.bd = bd; op.M = BATCH * LP; op.N = DM; op.K = NHEAD * HD;
        gemm_tc<<<dim3((DM + 127) / 128, (op.M + 127) / 128, 1), 256>>>(op);
    }
    ln_k<<<BATCH * LP, 128>>>(gamma, beta, out);
}

// round 9
// speedup vs baseline: 5.8857x; 1.0521x over previous
#include <cuda_runtime.h>
#include <math.h>
#include <stdint.h>

#define BATCH 2
#define NHEAD 8
#define DM 512
#define HD 512
#define TT 8
#define HH 28
#define WWW 28
#define LL 6273          // 1 + 8*28*28
#define LP 1569          // 1 + 8*14*14
#define LPP 1600         // padded K for attention GEMMs
#define NP 1568
#define BHN 16           // BATCH*NHEAD
#define ATT_SCALE 0.04419417382415922f   // 1/sqrt(512)

// ---------------- scratch (static device allocations) ----------------
__device__ __align__(256) float g_xr  [BATCH * LL * DM];       // rounded x
__device__ __align__(256) float g_Wdr [DM * NHEAD * HD];       // rounded Wd
__device__ __align__(256) float g_wp  [4][HD * 2048];          // packed+rounded pool weights [n][p*512+ci]
__device__ __align__(256) float g_WqT [3][DM * NHEAD * HD];    // rounded W^T: [d][h*512+ci]
__device__ __align__(256) float g_Weff[3 * NHEAD * HD * 2048]; // [s][h][co][p*512+d], rounded
__device__ __align__(256) float g_be  [3][NHEAD * HD];         // pooled bias
__device__ __align__(256) float g_PQ  [BHN * LP * HD];         // raw
__device__ __align__(256) float g_PQr [BHN * LP * HD];         // rounded
__device__ __align__(256) float g_PK  [BHN * LP * HD];         // raw (row0)
__device__ __align__(256) float g_PVt [BHN * HD * LPP];        // rounded, k-padded (pad stays 0)
__device__ __align__(256) float g_Kmod[BHN * LP * HD];         // rounded scale*PK+emb
__device__ __align__(256) float g_logits[BHN * LP * LPP];      // stride LPP
__device__ __align__(256) float g_att [BHN * LP * HD];         // rounded (+residual)
__device__ __align__(256) float g_PX  [BATCH * LP * HD];       // raw
__device__ __align__(256) float g_emb [NP * HD];
__device__ __align__(256) float g_y   [BATCH * LP * HD];

__device__ __forceinline__ float rnd32(float v) {
    unsigned u;
    asm("cvt.rna.tf32.f32 %0, %1;" : "=r"(u) : "f"(v));
    return __uint_as_float(u);
}

__device__ __forceinline__ void cp16(uint32_t dst, const float* src, bool valid) {
    if (valid)
        asm volatile("cp.async.cg.shared.global [%0], [%1], 16;\n" :: "r"(dst), "l"(src));
    else
        asm volatile("cp.async.cg.shared.global [%0], [%1], 16, %2;\n" :: "r"(dst), "l"(src), "r"(0));
}

// ---------------- tf32 GEMM: 128x128x16 tiles, 128 threads, 64x64 warp tile,
// ---------------- 3-stage cp.async pipeline, single syncthreads per k-step ----
#define RS 20
#define STAGE_F (2 * 128 * RS)                 // floats per stage (A+B)
#define SMEM_DYN (3 * STAGE_F * 4)             // 61440 bytes

template <class OP>
__global__ void __launch_bounds__(128, 2) gemm_tc(OP op) {
    extern __shared__ float sm[];
    __shared__ int aT[128], bT[128];

    const int z  = blockIdx.z;
    const int bm = blockIdx.y * 128;
    const int bn = blockIdx.x * 128;
    const int tid = threadIdx.x, lane = tid & 31;
    const int wid = tid >> 5;
    const int wm = (wid & 1) * 64, wn = (wid >> 1) * 64;
    const int r = lane >> 2, c = lane & 3;

    {
        int gm = bm + tid; aT[tid] = (gm < op.M) ? op.arow(z, gm) : -1;
        int gn = bn + tid; bT[tid] = (gn < op.N) ? op.brow(z, gn) : -1;
    }
    __syncthreads();

    const float* aB = op.abase(z);
    const float* bB = op.bbase(z);

    const int kq = tid & 3;                 // k-quad 0..3
    const int row = tid >> 2;               // 0..31
    int ao[4], bo[4];
#pragma unroll
    for (int i = 0; i < 4; i++) { ao[i] = aT[row + 32 * i]; bo[i] = bT[row + 32 * i]; }

    const uint32_t smu = (uint32_t)__cvta_generic_to_shared(sm);
    uint32_t dof[4];
#pragma unroll
    for (int i = 0; i < 4; i++) dof[i] = (uint32_t)((row + 32 * i) * RS + kq * 4) * 4u;

    float acc[4][8][4];
#pragma unroll
    for (int i = 0; i < 4; i++)
#pragma unroll
        for (int j = 0; j < 8; j++)
#pragma unroll
            for (int e = 0; e < 4; e++) acc[i][j][e] = 0.f;

    auto FETCH = [&](int kb, int st) {
        int gk = kb * 16 + kq * 4;
        int ak = op.akoff(gk), bk = op.bkoff(gk);
        uint32_t as = smu + (uint32_t)(st * STAGE_F) * 4u;
        uint32_t bs = as + (uint32_t)(128 * RS) * 4u;
#pragma unroll
        for (int i = 0; i < 4; i++) {
            cp16(as + dof[i], aB + (ao[i] < 0 ? 0 : ao[i] + ak), ao[i] >= 0);
            cp16(bs + dof[i], bB + (bo[i] < 0 ? 0 : bo[i] + bk), bo[i] >= 0);
        }
        asm volatile("cp.async.commit_group;\n" ::: "memory");
    };

    auto COMPUTE = [&](int st) {
        const float* A = sm + st * STAGE_F;
        const float* B = A + 128 * RS;
#pragma unroll
        for (int ks = 0; ks < 16; ks += 8) {
            unsigned af[4][4], bf[8][2];
#pragma unroll
            for (int mt = 0; mt < 4; mt++) {
                const float* p = A + (wm + mt * 16 + r) * RS + ks + c;
                af[mt][0] = __float_as_uint(p[0]);
                af[mt][1] = __float_as_uint(p[8 * RS]);
                af[mt][2] = __float_as_uint(p[4]);
                af[mt][3] = __float_as_uint(p[8 * RS + 4]);
            }
#pragma unroll
            for (int nt = 0; nt < 8; nt++) {
                const float* p = B + (wn + nt * 8 + r) * RS + ks + c;
                bf[nt][0] = __float_as_uint(p[0]);
                bf[nt][1] = __float_as_uint(p[4]);
            }
#pragma unroll
            for (int mt = 0; mt < 4; mt++)
#pragma unroll
                for (int nt = 0; nt < 8; nt++) {
                    asm volatile(
                        "mma.sync.aligned.m16n8k8.row.col.f32.tf32.tf32.f32 "
                        "{%0,%1,%2,%3}, {%4,%5,%6,%7}, {%8,%9}, {%0,%1,%2,%3};\n"
                        : "+f"(acc[mt][nt][0]), "+f"(acc[mt][nt][1]),
                          "+f"(acc[mt][nt][2]), "+f"(acc[mt][nt][3])
                        : "r"(af[mt][0]), "r"(af[mt][1]), "r"(af[mt][2]), "r"(af[mt][3]),
                          "r"(bf[nt][0]), "r"(bf[nt][1]));
                }
        }
    };

    const int nkb = op.K / 16;
    FETCH(0, 0);
    FETCH(1, 1);
    for (int kb = 0; kb < nkb; kb++) {
        if (kb + 1 < nkb)
            asm volatile("cp.async.wait_group 1;\n" ::: "memory");
        else
            asm volatile("cp.async.wait_group 0;\n" ::: "memory");
        __syncthreads();
        if (kb + 2 < nkb) FETCH(kb + 2, (kb + 2) % 3);
        COMPUTE(kb % 3);
    }

#pragma unroll
    for (int mt = 0; mt < 4; mt++) {
        int m0 = bm + wm + mt * 16 + r;
#pragma unroll
        for (int nt = 0; nt < 8; nt++) {
            int n0 = bn + wn + nt * 8 + 2 * c;
            if (m0 < op.M) {
                if (n0     < op.N) op.store(z, m0, n0,     acc[mt][nt][0]);
                if (n0 + 1 < op.N) op.store(z, m0, n0 + 1, acc[mt][nt][1]);
            }
            if (m0 + 8 < op.M) {
                if (n0     < op.N) op.store(z, m0 + 8, n0,     acc[mt][nt][2]);
                if (n0 + 1 < op.N) op.store(z, m0 + 8, n0 + 1, acc[mt][nt][3]);
            }
        }
    }
}

// ---------------- functors ----------------
// Weff[s,h,p][co,d] = sum_ci wp_s[co,ci,p] * W_s[h*512+ci, d];  z = s*32 + h*4 + p
struct OpWeff {
    const float* WqT0;
    int M, N, K;
    __device__ __forceinline__ const float* abase(int z) const {
        return g_wp[z >> 5];
    }
    __device__ __forceinline__ const float* bbase(int z) const {
        return WqT0 + (z >> 5) * (DM * NHEAD * HD);
    }
    __device__ __forceinline__ int arow(int z, int m) const {
        return m * 2048 + (z & 3) * 512;
    }
    __device__ __forceinline__ int akoff(int k) const { return k; }
    __device__ __forceinline__ int brow(int z, int n) const {
        return n * (NHEAD * HD) + ((z >> 2) & 7) * 512;
    }
    __device__ __forceinline__ int bkoff(int k) const { return k; }
    __device__ __forceinline__ void store(int z, int m, int n, float v) const {
        int s = z >> 5, h = (z >> 2) & 7, p = z & 3;
        g_Weff[(((s * NHEAD + h) * HD) + m) * 2048 + p * 512 + n] = rnd32(v);
    }
};

// pooled projection: z=(b,h); a = im2col(x), b = Weff[s,h]; K=2048
struct OpPoolP {
    int sel;             // 0=Q,1=K,2=V
    int M, N, K;
    __device__ __forceinline__ const float* abase(int) const { return g_xr; }
    __device__ __forceinline__ const float* bbase(int z) const {
        return g_Weff + (sel * NHEAD + (z & 7)) * (HD * 2048);
    }
    __device__ __forceinline__ int arow(int z, int m) const {
        int t = m / 196, rem = m % 196;
        int hy = rem / 14, wx = rem % 14;
        int l00 = 1 + (t * HH + 2 * hy) * WWW + 2 * wx;
        return ((z >> 3) * LL + l00) * DM;
    }
    __device__ __forceinline__ int akoff(int k) const {
        int p = k >> 9;
        return (k & 511) + ((p >> 1) * WWW + (p & 1)) * DM;
    }
    __device__ __forceinline__ int brow(int, int n) const { return n * 2048; }
    __device__ __forceinline__ int bkoff(int k) const { return k; }
    __device__ __forceinline__ void store(int z, int m, int n, float v) const {
        v += g_be[sel][(z & 7) * 512 + n];
        if (sel == 0) {
            int idx = (z * LP + 1 + m) * HD + n;
            g_PQ[idx] = v;
            g_PQr[idx] = rnd32(v);
        } else if (sel == 1) {
            int idx = (z * LP + 1 + m) * HD + n;
            g_PK[idx] = v;
            g_Kmod[idx] = rnd32(ATT_SCALE * v + g_emb[m * HD + n]);
        } else {
            g_PVt[(z * HD + n) * LPP + 1 + m] = rnd32(v);
        }
    }
};

// x pooling: z = b
struct OpPoolX {
    int M, N, K;
    __device__ __forceinline__ const float* abase(int) const { return g_xr; }
    __device__ __forceinline__ const float* bbase(int) const { return g_wp[3]; }
    __device__ __forceinline__ int arow(int z, int m) const {
        int t = m / 196, rem = m % 196;
        int hy = rem / 14, wx = rem % 14;
        int l00 = 1 + (t * HH + 2 * hy) * WWW + 2 * wx;
        return (z * LL + l00) * DM;
    }
    __device__ __forceinline__ int akoff(int k) const {
        int p = k >> 9;
        return (k & 511) + ((p >> 1) * WWW + (p & 1)) * DM;
    }
    __device__ __forceinline__ int brow(int, int n) const { return n * 2048; }
    __device__ __forceinline__ int bkoff(int k) const { return k; }
    __device__ __forceinline__ void store(int z, int m, int n, float v) const {
        g_PX[(z * LP + 1 + m) * HD + n] = v;
    }
};

struct OpLogits {
    int M, N, K;
    __device__ __forceinline__ const float* abase(int) const { return g_PQr; }
    __device__ __forceinline__ const float* bbase(int) const { return g_Kmod; }
    __device__ __forceinline__ int arow(int z, int m) const { return (z * LP + m) * HD; }
    __device__ __forceinline__ int akoff(int k) const { return k; }
    __device__ __forceinline__ int brow(int z, int n) const { return (z * LP + n) * HD; }
    __device__ __forceinline__ int bkoff(int k) const { return k; }
    __device__ __forceinline__ void store(int z, int m, int n, float v) const {
        g_logits[(z * LP + m) * LPP + n] = v;
    }
};

struct OpAV {
    int M, N, K;
    __device__ __forceinline__ const float* abase(int) const { return g_logits; }
    __device__ __forceinline__ const float* bbase(int) const { return g_PVt; }
    __device__ __forceinline__ int arow(int z, int m) const { return (z * LP + m) * LPP; }
    __device__ __forceinline__ int akoff(int k) const { return k; }
    __device__ __forceinline__ int brow(int z, int n) const { return (z * HD + n) * LPP; }
    __device__ __forceinline__ int bkoff(int k) const { return k; }
    __device__ __forceinline__ void store(int z, int m, int n, float v) const {
        float pq = g_PQ[(z * LP + m) * HD + n];
        g_att[(z * LP + m) * HD + n] = rnd32(v + (m == 0 ? 1.f : 2.f) * pq);
    }
};

struct OpY {
    const float* bd;
    int M, N, K;
    __device__ __forceinline__ const float* abase(int) const { return g_att; }
    __device__ __forceinline__ const float* bbase(int) const { return g_Wdr; }
    __device__ __forceinline__ int arow(int, int m) const {
        int bb = m / LP, q = m % LP;
        return (bb * NHEAD * LP + q) * HD;
    }
    __device__ __forceinline__ int akoff(int k) const {
        return (k >> 9) * (LP * HD) + (k & 511);
    }
    __device__ __forceinline__ int brow(int, int n) const { return n * (NHEAD * HD); }
    __device__ __forceinline__ int bkoff(int k) const { return k; }
    __device__ __forceinline__ void store(int, int m, int n, float v) const {
        g_y[m * DM + n] = v + bd[n] + g_PX[m * DM + n];
    }
};

// ---------------- small kernels ----------------
__global__ void round_k(float* dst, const float* src, int n) {
    int i = blockIdx.x * 256 + threadIdx.x;
    if (i < n) dst[i] = rnd32(src[i]);
}

__global__ void pack_k(float* dst, const float* src) {
    int i = blockIdx.x * 256 + threadIdx.x;
    if (i >= HD * 2048) return;
    int ci = i & 511, patch = (i >> 9) & 3, n = i >> 11;
    dst[n * 2048 + patch * 512 + ci] = rnd32(src[n * 2048 + ci * 4 + patch]);
}

__global__ void transW_k(const float* Wq, const float* Wk, const float* Wv) {
    __shared__ float t[32][33];
    int zz = blockIdx.z;
    const float* src = zz == 0 ? Wq : (zz == 1 ? Wk : Wv);
    float* dst = &g_WqT[zz][0];
    int bx = blockIdx.x * 32;
    int by = blockIdx.y * 32;
    int tx = threadIdx.x, ty = threadIdx.y;
#pragma unroll
    for (int i = 0; i < 4; i++)
        t[ty + i * 8][tx] = src[(by + ty + i * 8) * DM + bx + tx];
    __syncthreads();
#pragma unroll
    for (int i = 0; i < 4; i++)
        dst[(bx + ty + i * 8) * (NHEAD * HD) + by + tx] = rnd32(t[tx][ty + i * 8]);
}

__global__ void biaseff_k(const float* wpq, const float* wpk, const float* wpv,
                          const float* bq, const float* bk, const float* bv) {
    int s = blockIdx.y;
    const float* w = s == 0 ? wpq : (s == 1 ? wpk : wpv);
    const float* b = s == 0 ? bq : (s == 1 ? bk : bv);
    int gw = blockIdx.x * 8 + (threadIdx.x >> 5);
    int lane = threadIdx.x & 31;
    int h = gw >> 9, co = gw & 511;
    float sum = 0.f;
    for (int ci = lane; ci < 512; ci += 32) {
        const float* wp4 = w + co * 2048 + ci * 4;
        sum += (wp4[0] + wp4[1] + wp4[2] + wp4[3]) * b[h * 512 + ci];
    }
#pragma unroll
    for (int o = 16; o; o >>= 1) sum += __shfl_xor_sync(0xffffffffu, sum, o);
    if (lane == 0) g_be[s][gw] = sum;
}

__global__ void clsproj_k(const float* x,
                          const float* Wq, const float* Wk, const float* Wv,
                          const float* bq, const float* bk, const float* bv) {
    int s = blockIdx.y;
    const float* W = s == 0 ? Wq : (s == 1 ? Wk : Wv);
    const float* bb = s == 0 ? bq : (s == 1 ? bk : bv);
    int gw = blockIdx.x * 8 + (threadIdx.x >> 5);
    int lane = threadIdx.x & 31;
    int z = gw >> 9, c = gw & 511;
    int b = z >> 3, h = z & 7;
    const float* xr = x + (long long)b * LL * DM;
    const float* wr = W + (h * 512 + c) * DM;
    float sum = 0.f;
    for (int d = lane; d < DM; d += 32) sum += xr[d] * wr[d];
#pragma unroll
    for (int o = 16; o; o >>= 1) sum += __shfl_xor_sync(0xffffffffu, sum, o);
    if (lane == 0) {
        float v = sum + bb[h * 512 + c];
        if (s == 0) {
            g_PQ[z * LP * HD + c] = v;
            g_PQr[z * LP * HD + c] = rnd32(v);
        } else if (s == 1) {
            g_PK[z * LP * HD + c] = v;
            g_Kmod[z * LP * HD + c] = rnd32(ATT_SCALE * v);
        } else {
            g_PVt[(z * HD + c) * LPP] = rnd32(v);
        }
    }
}

__global__ void clsx_k(const float* x) {
    int i = blockIdx.x * 256 + threadIdx.x;
    if (i >= BATCH * DM) return;
    int z = i >> 9, c = i & 511;
    g_PX[z * LP * HD + c] = x[(long long)z * LL * DM + c];
}

__global__ void emb_k() {
    int i = blockIdx.x * 256 + threadIdx.x;
    if (i >= NP * HD) return;
    int tok = i >> 9, d = i & 511;
    int t = tok / 196, rem = tok % 196;
    int hy = rem / 14, wx = rem % 14;
    float pos; int j, half;
    if (d < 170)      { pos = (float)t;  j = d;        half = 85; }
    else if (d < 340) { pos = (float)hy; j = d - 170;  half = 85; }
    else              { pos = (float)wx; j = d - 340;  half = 86; }
    bool is_cos = (j >= half);
    int jj = is_cos ? j - half : j;
    float omega = powf(10000.f, -(float)jj / (float)half);
    float ang = pos * omega;
    g_emb[i] = is_cos ? cosf(ang) : sinf(ang);
}

__global__ void row0_k() {
    int w = (blockIdx.x * blockDim.x + threadIdx.x) >> 5;
    int lane = threadIdx.x & 31;
    if (w >= BHN * LP) return;
    int z = w / LP, n = w % LP;
    const float* q = g_PQ + z * LP * HD;
    const float* kk = g_PK + (z * LP + n) * HD;
    float s = 0.f;
    for (int i = lane; i < HD; i += 32) s += q[i] * kk[i];
#pragma unroll
    for (int o = 16; o; o >>= 1) s += __shfl_xor_sync(0xffffffffu, s, o);
    if (lane == 0) g_logits[(long long)z * LP * LPP + n] = s * ATT_SCALE;
}

__global__ void softmax_k() {
    int row = blockIdx.x;
    float* p = g_logits + (long long)row * LPP;
    int tid = threadIdx.x;
    float v[7];
    float m = -1e30f;
#pragma unroll
    for (int i = 0; i < 7; i++) {
        int idx = tid + i * 256;
        v[i] = (idx < LP) ? p[idx] : -1e30f;
        m = fmaxf(m, v[i]);
    }
    __shared__ float red[256];
    red[tid] = m; __syncthreads();
    for (int s = 128; s > 0; s >>= 1) {
        if (tid < s) red[tid] = fmaxf(red[tid], red[tid + s]);
        __syncthreads();
    }
    m = red[0]; __syncthreads();
    float sum = 0.f;
#pragma unroll
    for (int i = 0; i < 7; i++) {
        int idx = tid + i * 256;
        v[i] = (idx < LP) ? expf(v[i] - m) : 0.f;
        sum += v[i];
    }
    red[tid] = sum; __syncthreads();
    for (int s = 128; s > 0; s >>= 1) {
        if (tid < s) red[tid] += red[tid + s];
        __syncthreads();
    }
    float inv = 1.f / red[0];
#pragma unroll
    for (int i = 0; i < 7; i++) {
        int idx = tid + i * 256;
        if (idx < LP) p[idx] = rnd32(v[i] * inv);
    }
    if (tid < LPP - LP) p[LP + tid] = 0.f;
}

__global__ void ln_k(const float* gamma, const float* beta, float* out) {
    int row = blockIdx.x;
    const float* p = g_y + row * DM;
    int tid = threadIdx.x;
    float v[4];
#pragma unroll
    for (int i = 0; i < 4; i++) v[i] = p[tid + i * 128];
    __shared__ float red[128];
    float s = v[0] + v[1] + v[2] + v[3];
    red[tid] = s; __syncthreads();
    for (int st = 64; st > 0; st >>= 1) {
        if (tid < st) red[tid] += red[tid + st];
        __syncthreads();
    }
    float mu = red[0] / (float)DM;
    __syncthreads();
    float sq = 0.f;
#pragma unroll
    for (int i = 0; i < 4; i++) { float d = v[i] - mu; sq += d * d; }
    red[tid] = sq; __syncthreads();
    for (int st = 64; st > 0; st >>= 1) {
        if (tid < st) red[tid] += red[tid + st];
        __syncthreads();
    }
    float inv = rsqrtf(red[0] / (float)DM + 1e-5f);
    __syncthreads();
#pragma unroll
    for (int i = 0; i < 4; i++) {
        int cc = tid + i * 128;
        out[row * DM + cc] = (v[i] - mu) * inv * gamma[cc] + beta[cc];
    }
}

// ---------------- launch ----------------
extern "C" void kernel_launch(void* const* d_in, const int* in_sizes, int n_in,
                              void* d_out, int out_size) {
    const float* x    = (const float*)d_in[0];
    const float* Wq   = (const float*)d_in[1];
    const float* bq   = (const float*)d_in[2];
    const float* Wk   = (const float*)d_in[3];
    const float* bk   = (const float*)d_in[4];
    const float* Wv   = (const float*)d_in[5];
    const float* bv   = (const float*)d_in[6];
    const float* wpq  = (const float*)d_in[7];
    const float* wpk  = (const float*)d_in[8];
    const float* wpv  = (const float*)d_in[9];
    const float* wpx  = (const float*)d_in[10];
    const float* Wd   = (const float*)d_in[11];
    const float* bd   = (const float*)d_in[12];
    const float* gamma= (const float*)d_in[13];
    const float* beta = (const float*)d_in[14];
    float* out = (float*)d_out;

    float *p_xr, *p_Wdr, *p_wp, *p_WqT;
    cudaGetSymbolAddress((void**)&p_xr,  g_xr);
    cudaGetSymbolAddress((void**)&p_Wdr, g_Wdr);
    cudaGetSymbolAddress((void**)&p_wp,  g_wp);
    cudaGetSymbolAddress((void**)&p_WqT, g_WqT);

    cudaFuncSetAttribute(gemm_tc<OpWeff>,   cudaFuncAttributeMaxDynamicSharedMemorySize, SMEM_DYN);
    cudaFuncSetAttribute(gemm_tc<OpPoolP>,  cudaFuncAttributeMaxDynamicSharedMemorySize, SMEM_DYN);
    cudaFuncSetAttribute(gemm_tc<OpPoolX>,  cudaFuncAttributeMaxDynamicSharedMemorySize, SMEM_DYN);
    cudaFuncSetAttribute(gemm_tc<OpLogits>, cudaFuncAttributeMaxDynamicSharedMemorySize, SMEM_DYN);
    cudaFuncSetAttribute(gemm_tc<OpAV>,     cudaFuncAttributeMaxDynamicSharedMemorySize, SMEM_DYN);
    cudaFuncSetAttribute(gemm_tc<OpY>,      cudaFuncAttributeMaxDynamicSharedMemorySize, SMEM_DYN);

    // 0) prep
    int nx = BATCH * LL * DM;
    round_k<<<(nx + 255) / 256, 256>>>(p_xr, x, nx);
    int nw = NHEAD * HD * DM;
    round_k<<<(nw + 255) / 256, 256>>>(p_Wdr, Wd, nw);
    int npk = HD * 2048;
    pack_k<<<(npk + 255) / 256, 256>>>(p_wp + 0 * npk, wpq);
    pack_k<<<(npk + 255) / 256, 256>>>(p_wp + 1 * npk, wpk);
    pack_k<<<(npk + 255) / 256, 256>>>(p_wp + 2 * npk, wpv);
    pack_k<<<(npk + 255) / 256, 256>>>(p_wp + 3 * npk, wpx);
    transW_k<<<dim3(16, 128, 3), dim3(32, 8)>>>(Wq, Wk, Wv);
    emb_k<<<(NP * HD + 255) / 256, 256>>>();
    biaseff_k<<<dim3(512, 3), 256>>>(wpq, wpk, wpv, bq, bk, bv);

    // 1) Weff = wpool @ W
    {
        OpWeff op; op.WqT0 = p_WqT; op.M = 512; op.N = 512; op.K = 512;
        gemm_tc<<<dim3(4, 4, 96), 128, SMEM_DYN>>>(op);
    }

    // 2) fused pooled projections + x-pool + cls
    {
        OpPoolP op; op.M = NP; op.N = HD; op.K = 2048;
        dim3 g(4, (NP + 127) / 128, BHN);
        op.sel = 0; gemm_tc<<<g, 128, SMEM_DYN>>>(op);
        op.sel = 1; gemm_tc<<<g, 128, SMEM_DYN>>>(op);
        op.sel = 2; gemm_tc<<<g, 128, SMEM_DYN>>>(op);
    }
    {
        OpPoolX op; op.M = NP; op.N = HD; op.K = 2048;
        gemm_tc<<<dim3(4, (NP + 127) / 128, BATCH), 128, SMEM_DYN>>>(op);
    }
    clsproj_k<<<dim3(1024, 3), 256>>>(x, Wq, Wk, Wv, bq, bk, bv);
    clsx_k<<<(BATCH * DM + 255) / 256, 256>>>(x);

    // 3) logits GEMM, row-0 repair, softmax
    {
        OpLogits op; op.M = LP; op.N = LP; op.K = HD;
        gemm_tc<<<dim3((LP + 127) / 128, (LP + 127) / 128, BHN), 128, SMEM_DYN>>>(op);
    }
    row0_k<<<(BHN * LP * 32 + 255) / 256, 256>>>();
    softmax_k<<<BHN * LP, 256>>>();

    // 4) attn @ PV (+residual)
    {
        OpAV op; op.M = LP; op.N = HD; op.K = LPP;
        gemm_tc<<<dim3((HD + 127) / 128, (LP + 127) / 128, BHN), 128, SMEM_DYN>>>(op);
    }

    // 5) output projection + bias + PX, then LayerNorm
    {
        OpY op; op.bd = bd; op.M = BATCH * LP; op.N = DM; op.K = NHEAD * HD;
        gemm_tc<<<dim3((DM + 127) / 128, (op.M + 127) / 128, 1), 128, SMEM_DYN>>>(op);
    }
    ln_k<<<BATCH * LP, 128>>>(gamma, beta, out);
}

// round 10
// speedup vs baseline: 8.6781x; 1.4744x over previous
#include <cuda_runtime.h>
#include <cuda_fp16.h>
#include <math.h>
#include <stdint.h>

#define BATCH 2
#define NHEAD 8
#define DM 512
#define HD 512
#define TT 8
#define HH 28
#define WWW 28
#define LL 6273          // 1 + 8*28*28
#define LP 1569          // 1 + 8*14*14
#define LPP 1600         // padded K for attention GEMMs
#define NP 1568
#define BHN 16           // BATCH*NHEAD
#define ATT_SCALE 0.04419417382415922f   // 1/sqrt(512)

// ---------------- scratch (static device allocations) ----------------
__device__ __align__(256) __half g_xr  [BATCH * LL * DM];       // half x
__device__ __align__(256) __half g_Wdr [DM * NHEAD * HD];       // half Wd
__device__ __align__(256) __half g_wp  [4][HD * 2048];          // packed half pool weights [n][p*512+ci]
__device__ __align__(256) __half g_WqT [3][DM * NHEAD * HD];    // half W^T: [d][h*512+ci]
__device__ __align__(256) __half g_Weff[3 * NHEAD * HD * 2048]; // [s][h][co][p*512+d]
__device__ __align__(256) float  g_be  [3][NHEAD * HD];         // pooled bias (fp32)
__device__ __align__(256) float  g_PQ  [BHN * LP * HD];         // raw fp32 (residual / row0)
__device__ __align__(256) __half g_PQr [BHN * LP * HD];         // half (logits a)
__device__ __align__(256) float  g_PK  [BHN * LP * HD];         // raw fp32 (row0)
__device__ __align__(256) __half g_PVt [BHN * HD * LPP];        // half, k-padded (pad stays 0)
__device__ __align__(256) __half g_Kmod[BHN * LP * HD];         // half scale*PK+emb
__device__ __align__(256) float  g_logits[BHN * LP * LPP];      // fp32, stride LPP
__device__ __align__(256) __half g_probs[BHN * LP * LPP];       // half probs, pad zero
__device__ __align__(256) __half g_att [BHN * LP * HD];         // half (+residual)
__device__ __align__(256) float  g_PX  [BATCH * LP * HD];       // fp32
__device__ __align__(256) float  g_emb [NP * HD];
__device__ __align__(256) float  g_y   [BATCH * LP * HD];

__device__ __forceinline__ __half h16(float v) { return __float2half_rn(v); }

__device__ __forceinline__ void cp16(uint32_t dst, const __half* src, bool valid) {
    if (valid)
        asm volatile("cp.async.cg.shared.global [%0], [%1], 16;\n" :: "r"(dst), "l"(src));
    else
        asm volatile("cp.async.cg.shared.global [%0], [%1], 16, %2;\n" :: "r"(dst), "l"(src), "r"(0));
}

// ---------------- fp16 GEMM: 128x128x16 tiles, 128 threads, 64x64 warp tile,
// ---------------- 4-stage cp.async pipeline, 1 syncthreads per k-step --------
#define RSH 24                                   // halves per smem row (16 data + 8 pad)
#define STAGE_H (2 * 128 * RSH)                  // halves per stage (A+B)
#define SMEM_DYN (4 * STAGE_H * 2)               // 49152 bytes

template <class OP>
__global__ void __launch_bounds__(128, 2) gemm_tc(OP op) {
    extern __shared__ __half smh[];
    __shared__ int aT[128], bT[128];

    const int z  = blockIdx.z;
    const int bm = blockIdx.y * 128;
    const int bn = blockIdx.x * 128;
    const int tid = threadIdx.x, lane = tid & 31;
    const int wid = tid >> 5;
    const int wm = (wid & 1) * 64, wn = (wid >> 1) * 64;
    const int r = lane >> 2, c = lane & 3;

    {
        int gm = bm + tid; aT[tid] = (gm < op.M) ? op.arow(z, gm) : -1;
        int gn = bn + tid; bT[tid] = (gn < op.N) ? op.brow(z, gn) : -1;
    }
    __syncthreads();

    const __half* aB = op.abase(z);
    const __half* bB = op.bbase(z);

    const int khalf = tid & 1;                  // which 8-half chunk of the 16-k row
    const int rr = tid >> 1;                    // 0..63
    const int ao0 = aT[rr], ao1 = aT[rr + 64];
    const int bo0 = bT[rr], bo1 = bT[rr + 64];

    const uint32_t smu = (uint32_t)__cvta_generic_to_shared(smh);
    const uint32_t d0 = (uint32_t)(rr * RSH + khalf * 8) * 2u;
    const uint32_t d1 = (uint32_t)((rr + 64) * RSH + khalf * 8) * 2u;

    float acc[4][8][4];
#pragma unroll
    for (int i = 0; i < 4; i++)
#pragma unroll
        for (int j = 0; j < 8; j++)
#pragma unroll
            for (int e = 0; e < 4; e++) acc[i][j][e] = 0.f;

    auto FETCH = [&](int kb, int st) {
        int gk = kb * 16 + khalf * 8;
        int ak = op.akoff(gk), bk = op.bkoff(gk);
        uint32_t as = smu + (uint32_t)(st * STAGE_H) * 2u;
        uint32_t bs = as + (uint32_t)(128 * RSH) * 2u;
        cp16(as + d0, aB + (ao0 < 0 ? 0 : ao0 + ak), ao0 >= 0);
        cp16(as + d1, aB + (ao1 < 0 ? 0 : ao1 + ak), ao1 >= 0);
        cp16(bs + d0, bB + (bo0 < 0 ? 0 : bo0 + bk), bo0 >= 0);
        cp16(bs + d1, bB + (bo1 < 0 ? 0 : bo1 + bk), bo1 >= 0);
        asm volatile("cp.async.commit_group;\n" ::: "memory");
    };

    auto COMPUTE = [&](int st) {
        const __half* A = smh + st * STAGE_H;
        const __half* B = A + 128 * RSH;
        unsigned af[4][4], bf[8][2];
#pragma unroll
        for (int mt = 0; mt < 4; mt++) {
            const __half* p = A + (wm + mt * 16 + r) * RSH + 2 * c;
            af[mt][0] = *(const unsigned*)(p);
            af[mt][1] = *(const unsigned*)(p + 8 * RSH);
            af[mt][2] = *(const unsigned*)(p + 8);
            af[mt][3] = *(const unsigned*)(p + 8 * RSH + 8);
        }
#pragma unroll
        for (int nt = 0; nt < 8; nt++) {
            const __half* q = B + (wn + nt * 8 + r) * RSH + 2 * c;
            bf[nt][0] = *(const unsigned*)(q);
            bf[nt][1] = *(const unsigned*)(q + 8);
        }
#pragma unroll
        for (int mt = 0; mt < 4; mt++)
#pragma unroll
            for (int nt = 0; nt < 8; nt++) {
                asm volatile(
                    "mma.sync.aligned.m16n8k16.row.col.f32.f16.f16.f32 "
                    "{%0,%1,%2,%3}, {%4,%5,%6,%7}, {%8,%9}, {%0,%1,%2,%3};\n"
                    : "+f"(acc[mt][nt][0]), "+f"(acc[mt][nt][1]),
                      "+f"(acc[mt][nt][2]), "+f"(acc[mt][nt][3])
                    : "r"(af[mt][0]), "r"(af[mt][1]), "r"(af[mt][2]), "r"(af[mt][3]),
                      "r"(bf[nt][0]), "r"(bf[nt][1]));
            }
    };

    const int nkb = op.K / 16;
    FETCH(0, 0);
    if (nkb > 1) FETCH(1, 1);
    if (nkb > 2) FETCH(2, 2);
    for (int kb = 0; kb < nkb; kb++) {
        int rem = nkb - kb - 1;
        if (rem >= 2)      asm volatile("cp.async.wait_group 2;\n" ::: "memory");
        else if (rem == 1) asm volatile("cp.async.wait_group 1;\n" ::: "memory");
        else               asm volatile("cp.async.wait_group 0;\n" ::: "memory");
        __syncthreads();
        if (kb + 3 < nkb) FETCH(kb + 3, (kb + 3) & 3);
        COMPUTE(kb & 3);
    }

#pragma unroll
    for (int mt = 0; mt < 4; mt++) {
        int m0 = bm + wm + mt * 16 + r;
#pragma unroll
        for (int nt = 0; nt < 8; nt++) {
            int n0 = bn + wn + nt * 8 + 2 * c;
            if (m0 < op.M) {
                if (n0     < op.N) op.store(z, m0, n0,     acc[mt][nt][0]);
                if (n0 + 1 < op.N) op.store(z, m0, n0 + 1, acc[mt][nt][1]);
            }
            if (m0 + 8 < op.M) {
                if (n0     < op.N) op.store(z, m0 + 8, n0,     acc[mt][nt][2]);
                if (n0 + 1 < op.N) op.store(z, m0 + 8, n0 + 1, acc[mt][nt][3]);
            }
        }
    }
}

// ---------------- functors ----------------
// Weff[s,h,p][co,d] = sum_ci wp_s[co,ci,p] * W_s[h*512+ci, d];  z = s*32 + h*4 + p
struct OpWeff {
    int M, N, K;
    __device__ __forceinline__ const __half* abase(int z) const {
        return g_wp[z >> 5];
    }
    __device__ __forceinline__ const __half* bbase(int z) const {
        return &g_WqT[z >> 5][0];
    }
    __device__ __forceinline__ int arow(int z, int m) const {
        return m * 2048 + (z & 3) * 512;
    }
    __device__ __forceinline__ int akoff(int k) const { return k; }
    __device__ __forceinline__ int brow(int z, int n) const {
        return n * (NHEAD * HD) + ((z >> 2) & 7) * 512;
    }
    __device__ __forceinline__ int bkoff(int k) const { return k; }
    __device__ __forceinline__ void store(int z, int m, int n, float v) const {
        int s = z >> 5, h = (z >> 2) & 7, p = z & 3;
        g_Weff[(((s * NHEAD + h) * HD) + m) * 2048 + p * 512 + n] = h16(v);
    }
};

// pooled projection: z=(b,h); a = im2col(x), b = Weff[s,h]; K=2048
struct OpPoolP {
    int sel;             // 0=Q,1=K,2=V
    int M, N, K;
    __device__ __forceinline__ const __half* abase(int) const { return g_xr; }
    __device__ __forceinline__ const __half* bbase(int z) const {
        return g_Weff + (sel * NHEAD + (z & 7)) * (HD * 2048);
    }
    __device__ __forceinline__ int arow(int z, int m) const {
        int t = m / 196, rem = m % 196;
        int hy = rem / 14, wx = rem % 14;
        int l00 = 1 + (t * HH + 2 * hy) * WWW + 2 * wx;
        return ((z >> 3) * LL + l00) * DM;
    }
    __device__ __forceinline__ int akoff(int k) const {
        int p = k >> 9;
        return (k & 511) + ((p >> 1) * WWW + (p & 1)) * DM;
    }
    __device__ __forceinline__ int brow(int, int n) const { return n * 2048; }
    __device__ __forceinline__ int bkoff(int k) const { return k; }
    __device__ __forceinline__ void store(int z, int m, int n, float v) const {
        v += g_be[sel][(z & 7) * 512 + n];
        if (sel == 0) {
            int idx = (z * LP + 1 + m) * HD + n;
            g_PQ[idx] = v;
            g_PQr[idx] = h16(v);
        } else if (sel == 1) {
            int idx = (z * LP + 1 + m) * HD + n;
            g_PK[idx] = v;
            g_Kmod[idx] = h16(ATT_SCALE * v + g_emb[m * HD + n]);
        } else {
            g_PVt[(z * HD + n) * LPP + 1 + m] = h16(v);
        }
    }
};

// x pooling: z = b
struct OpPoolX {
    int M, N, K;
    __device__ __forceinline__ const __half* abase(int) const { return g_xr; }
    __device__ __forceinline__ const __half* bbase(int) const { return g_wp[3]; }
    __device__ __forceinline__ int arow(int z, int m) const {
        int t = m / 196, rem = m % 196;
        int hy = rem / 14, wx = rem % 14;
        int l00 = 1 + (t * HH + 2 * hy) * WWW + 2 * wx;
        return (z * LL + l00) * DM;
    }
    __device__ __forceinline__ int akoff(int k) const {
        int p = k >> 9;
        return (k & 511) + ((p >> 1) * WWW + (p & 1)) * DM;
    }
    __device__ __forceinline__ int brow(int, int n) const { return n * 2048; }
    __device__ __forceinline__ int bkoff(int k) const { return k; }
    __device__ __forceinline__ void store(int z, int m, int n, float v) const {
        g_PX[(z * LP + 1 + m) * HD + n] = v;
    }
};

struct OpLogits {
    int M, N, K;
    __device__ __forceinline__ const __half* abase(int) const { return g_PQr; }
    __device__ __forceinline__ const __half* bbase(int) const { return g_Kmod; }
    __device__ __forceinline__ int arow(int z, int m) const { return (z * LP + m) * HD; }
    __device__ __forceinline__ int akoff(int k) const { return k; }
    __device__ __forceinline__ int brow(int z, int n) const { return (z * LP + n) * HD; }
    __device__ __forceinline__ int bkoff(int k) const { return k; }
    __device__ __forceinline__ void store(int z, int m, int n, float v) const {
        g_logits[(z * LP + m) * LPP + n] = v;
    }
};

struct OpAV {
    int M, N, K;
    __device__ __forceinline__ const __half* abase(int) const { return g_probs; }
    __device__ __forceinline__ const __half* bbase(int) const { return g_PVt; }
    __device__ __forceinline__ int arow(int z, int m) const { return (z * LP + m) * LPP; }
    __device__ __forceinline__ int akoff(int k) const { return k; }
    __device__ __forceinline__ int brow(int z, int n) const { return (z * HD + n) * LPP; }
    __device__ __forceinline__ int bkoff(int k) const { return k; }
    __device__ __forceinline__ void store(int z, int m, int n, float v) const {
        float pq = g_PQ[(z * LP + m) * HD + n];
        g_att[(z * LP + m) * HD + n] = h16(v + (m == 0 ? 1.f : 2.f) * pq);
    }
};

struct OpY {
    const float* bd;
    int M, N, K;
    __device__ __forceinline__ const __half* abase(int) const { return g_att; }
    __device__ __forceinline__ const __half* bbase(int) const { return g_Wdr; }
    __device__ __forceinline__ int arow(int, int m) const {
        int bb = m / LP, q = m % LP;
        return (bb * NHEAD * LP + q) * HD;
    }
    __device__ __forceinline__ int akoff(int k) const {
        return (k >> 9) * (LP * HD) + (k & 511);
    }
    __device__ __forceinline__ int brow(int, int n) const { return n * (NHEAD * HD); }
    __device__ __forceinline__ int bkoff(int k) const { return k; }
    __device__ __forceinline__ void store(int, int m, int n, float v) const {
        g_y[m * DM + n] = v + bd[n] + g_PX[m * DM + n];
    }
};

// ---------------- small kernels ----------------
__global__ void round_k(__half* dst, const float* src, int n) {
    int i = blockIdx.x * 256 + threadIdx.x;
    if (i < n) dst[i] = h16(src[i]);
}

__global__ void pack_k(__half* dst, const float* src) {
    int i = blockIdx.x * 256 + threadIdx.x;
    if (i >= HD * 2048) return;
    int ci = i & 511, patch = (i >> 9) & 3, n = i >> 11;
    dst[n * 2048 + patch * 512 + ci] = h16(src[n * 2048 + ci * 4 + patch]);
}

__global__ void transW_k(const float* Wq, const float* Wk, const float* Wv) {
    __shared__ float t[32][33];
    int zz = blockIdx.z;
    const float* src = zz == 0 ? Wq : (zz == 1 ? Wk : Wv);
    __half* dst = &g_WqT[zz][0];
    int bx = blockIdx.x * 32;
    int by = blockIdx.y * 32;
    int tx = threadIdx.x, ty = threadIdx.y;
#pragma unroll
    for (int i = 0; i < 4; i++)
        t[ty + i * 8][tx] = src[(by + ty + i * 8) * DM + bx + tx];
    __syncthreads();
#pragma unroll
    for (int i = 0; i < 4; i++)
        dst[(bx + ty + i * 8) * (NHEAD * HD) + by + tx] = h16(t[tx][ty + i * 8]);
}

__global__ void biaseff_k(const float* wpq, const float* wpk, const float* wpv,
                          const float* bq, const float* bk, const float* bv) {
    int s = blockIdx.y;
    const float* w = s == 0 ? wpq : (s == 1 ? wpk : wpv);
    const float* b = s == 0 ? bq : (s == 1 ? bk : bv);
    int gw = blockIdx.x * 8 + (threadIdx.x >> 5);
    int lane = threadIdx.x & 31;
    int h = gw >> 9, co = gw & 511;
    float sum = 0.f;
    for (int ci = lane; ci < 512; ci += 32) {
        const float* wp4 = w + co * 2048 + ci * 4;
        sum += (wp4[0] + wp4[1] + wp4[2] + wp4[3]) * b[h * 512 + ci];
    }
#pragma unroll
    for (int o = 16; o; o >>= 1) sum += __shfl_xor_sync(0xffffffffu, sum, o);
    if (lane == 0) g_be[s][gw] = sum;
}

__global__ void clsproj_k(const float* x,
                          const float* Wq, const float* Wk, const float* Wv,
                          const float* bq, const float* bk, const float* bv) {
    int s = blockIdx.y;
    const float* W = s == 0 ? Wq : (s == 1 ? Wk : Wv);
    const float* bb = s == 0 ? bq : (s == 1 ? bk : bv);
    int gw = blockIdx.x * 8 + (threadIdx.x >> 5);
    int lane = threadIdx.x & 31;
    int z = gw >> 9, c = gw & 511;
    int b = z >> 3, h = z & 7;
    const float* xr = x + (long long)b * LL * DM;
    const float* wr = W + (h * 512 + c) * DM;
    float sum = 0.f;
    for (int d = lane; d < DM; d += 32) sum += xr[d] * wr[d];
#pragma unroll
    for (int o = 16; o; o >>= 1) sum += __shfl_xor_sync(0xffffffffu, sum, o);
    if (lane == 0) {
        float v = sum + bb[h * 512 + c];
        if (s == 0) {
            g_PQ[z * LP * HD + c] = v;
            g_PQr[z * LP * HD + c] = h16(v);
        } else if (s == 1) {
            g_PK[z * LP * HD + c] = v;
            g_Kmod[z * LP * HD + c] = h16(ATT_SCALE * v);
        } else {
            g_PVt[(z * HD + c) * LPP] = h16(v);
        }
    }
}

__global__ void clsx_k(const float* x) {
    int i = blockIdx.x * 256 + threadIdx.x;
    if (i >= BATCH * DM) return;
    int z = i >> 9, c = i & 511;
    g_PX[z * LP * HD + c] = x[(long long)z * LL * DM + c];
}

__global__ void emb_k() {
    int i = blockIdx.x * 256 + threadIdx.x;
    if (i >= NP * HD) return;
    int tok = i >> 9, d = i & 511;
    int t = tok / 196, rem = tok % 196;
    int hy = rem / 14, wx = rem % 14;
    float pos; int j, half;
    if (d < 170)      { pos = (float)t;  j = d;        half = 85; }
    else if (d < 340) { pos = (float)hy; j = d - 170;  half = 85; }
    else              { pos = (float)wx; j = d - 340;  half = 86; }
    bool is_cos = (j >= half);
    int jj = is_cos ? j - half : j;
    float omega = powf(10000.f, -(float)jj / (float)half);
    float ang = pos * omega;
    g_emb[i] = is_cos ? cosf(ang) : sinf(ang);
}

__global__ void row0_k() {
    int w = (blockIdx.x * blockDim.x + threadIdx.x) >> 5;
    int lane = threadIdx.x & 31;
    if (w >= BHN * LP) return;
    int z = w / LP, n = w % LP;
    const float* q = g_PQ + z * LP * HD;
    const float* kk = g_PK + (z * LP + n) * HD;
    float s = 0.f;
    for (int i = lane; i < HD; i += 32) s += q[i] * kk[i];
#pragma unroll
    for (int o = 16; o; o >>= 1) s += __shfl_xor_sync(0xffffffffu, s, o);
    if (lane == 0) g_logits[(long long)z * LP * LPP + n] = s * ATT_SCALE;
}

__global__ void softmax_k() {
    int row = blockIdx.x;
    float* p = g_logits + (long long)row * LPP;
    __half* pr = g_probs + (long long)row * LPP;
    int tid = threadIdx.x;
    float v[7];
    float m = -1e30f;
#pragma unroll
    for (int i = 0; i < 7; i++) {
        int idx = tid + i * 256;
        v[i] = (idx < LP) ? p[idx] : -1e30f;
        m = fmaxf(m, v[i]);
    }
    __shared__ float red[256];
    red[tid] = m; __syncthreads();
    for (int s = 128; s > 0; s >>= 1) {
        if (tid < s) red[tid] = fmaxf(red[tid], red[tid + s]);
        __syncthreads();
    }
    m = red[0]; __syncthreads();
    float sum = 0.f;
#pragma unroll
    for (int i = 0; i < 7; i++) {
        int idx = tid + i * 256;
        v[i] = (idx < LP) ? expf(v[i] - m) : 0.f;
        sum += v[i];
    }
    red[tid] = sum; __syncthreads();
    for (int s = 128; s > 0; s >>= 1) {
        if (tid < s) red[tid] += red[tid + s];
        __syncthreads();
    }
    float inv = 1.f / red[0];
#pragma unroll
    for (int i = 0; i < 7; i++) {
        int idx = tid + i * 256;
        if (idx < LP) pr[idx] = h16(v[i] * inv);
    }
    if (tid < LPP - LP) pr[LP + tid] = __float2half(0.f);
}

__global__ void ln_k(const float* gamma, const float* beta, float* out) {
    int row = blockIdx.x;
    const float* p = g_y + row * DM;
    int tid = threadIdx.x;
    float v[4];
#pragma unroll
    for (int i = 0; i < 4; i++) v[i] = p[tid + i * 128];
    __shared__ float red[128];
    float s = v[0] + v[1] + v[2] + v[3];
    red[tid] = s; __syncthreads();
    for (int st = 64; st > 0; st >>= 1) {
        if (tid < st) red[tid] += red[tid + st];
        __syncthreads();
    }
    float mu = red[0] / (float)DM;
    __syncthreads();
    float sq = 0.f;
#pragma unroll
    for (int i = 0; i < 4; i++) { float d = v[i] - mu; sq += d * d; }
    red[tid] = sq; __syncthreads();
    for (int st = 64; st > 0; st >>= 1) {
        if (tid < st) red[tid] += red[tid + st];
        __syncthreads();
    }
    float inv = rsqrtf(red[0] / (float)DM + 1e-5f);
    __syncthreads();
#pragma unroll
    for (int i = 0; i < 4; i++) {
        int cc = tid + i * 128;
        out[row * DM + cc] = (v[i] - mu) * inv * gamma[cc] + beta[cc];
    }
}

// ---------------- launch ----------------
extern "C" void kernel_launch(void* const* d_in, const int* in_sizes, int n_in,
                              void* d_out, int out_size) {
    const float* x    = (const float*)d_in[0];
    const float* Wq   = (const float*)d_in[1];
    const float* bq   = (const float*)d_in[2];
    const float* Wk   = (const float*)d_in[3];
    const float* bk   = (const float*)d_in[4];
    const float* Wv   = (const float*)d_in[5];
    const float* bv   = (const float*)d_in[6];
    const float* wpq  = (const float*)d_in[7];
    const float* wpk  = (const float*)d_in[8];
    const float* wpv  = (const float*)d_in[9];
    const float* wpx  = (const float*)d_in[10];
    const float* Wd   = (const float*)d_in[11];
    const float* bd   = (const float*)d_in[12];
    const float* gamma= (const float*)d_in[13];
    const float* beta = (const float*)d_in[14];
    float* out = (float*)d_out;

    __half *p_xr, *p_Wdr, *p_wp;
    cudaGetSymbolAddress((void**)&p_xr,  g_xr);
    cudaGetSymbolAddress((void**)&p_Wdr, g_Wdr);
    cudaGetSymbolAddress((void**)&p_wp,  g_wp);

    cudaFuncSetAttribute(gemm_tc<OpWeff>,   cudaFuncAttributeMaxDynamicSharedMemorySize, SMEM_DYN);
    cudaFuncSetAttribute(gemm_tc<OpPoolP>,  cudaFuncAttributeMaxDynamicSharedMemorySize, SMEM_DYN);
    cudaFuncSetAttribute(gemm_tc<OpPoolX>,  cudaFuncAttributeMaxDynamicSharedMemorySize, SMEM_DYN);
    cudaFuncSetAttribute(gemm_tc<OpLogits>, cudaFuncAttributeMaxDynamicSharedMemorySize, SMEM_DYN);
    cudaFuncSetAttribute(gemm_tc<OpAV>,     cudaFuncAttributeMaxDynamicSharedMemorySize, SMEM_DYN);
    cudaFuncSetAttribute(gemm_tc<OpY>,      cudaFuncAttributeMaxDynamicSharedMemorySize, SMEM_DYN);

    // 0) prep
    int nx = BATCH * LL * DM;
    round_k<<<(nx + 255) / 256, 256>>>(p_xr, x, nx);
    int nw = NHEAD * HD * DM;
    round_k<<<(nw + 255) / 256, 256>>>(p_Wdr, Wd, nw);
    int npk = HD * 2048;
    pack_k<<<(npk + 255) / 256, 256>>>(p_wp + 0 * npk, wpq);
    pack_k<<<(npk + 255) / 256, 256>>>(p_wp + 1 * npk, wpk);
    pack_k<<<(npk + 255) / 256, 256>>>(p_wp + 2 * npk, wpv);
    pack_k<<<(npk + 255) / 256, 256>>>(p_wp + 3 * npk, wpx);
    transW_k<<<dim3(16, 128, 3), dim3(32, 8)>>>(Wq, Wk, Wv);
    emb_k<<<(NP * HD + 255) / 256, 256>>>();
    biaseff_k<<<dim3(512, 3), 256>>>(wpq, wpk, wpv, bq, bk, bv);

    // 1) Weff = wpool @ W
    {
        OpWeff op; op.M = 512; op.N = 512; op.K = 512;
        gemm_tc<<<dim3(4, 4, 96), 128, SMEM_DYN>>>(op);
    }

    // 2) fused pooled projections + x-pool + cls
    {
        OpPoolP op; op.M = NP; op.N = HD; op.K = 2048;
        dim3 g(4, (NP + 127) / 128, BHN);
        op.sel = 0; gemm_tc<<<g, 128, SMEM_DYN>>>(op);
        op.sel = 1; gemm_tc<<<g, 128, SMEM_DYN>>>(op);
        op.sel = 2; gemm_tc<<<g, 128, SMEM_DYN>>>(op);
    }
    {
        OpPoolX op; op.M = NP; op.N = HD; op.K = 2048;
        gemm_tc<<<dim3(4, (NP + 127) / 128, BATCH), 128, SMEM_DYN>>>(op);
    }
    clsproj_k<<<dim3(1024, 3), 256>>>(x, Wq, Wk, Wv, bq, bk, bv);
    clsx_k<<<(BATCH * DM + 255) / 256, 256>>>(x);

    // 3) logits GEMM, row-0 repair, softmax
    {
        OpLogits op; op.M = LP; op.N = LP; op.K = HD;
        gemm_tc<<<dim3((LP + 127) / 128, (LP + 127) / 128, BHN), 128, SMEM_DYN>>>(op);
    }
    row0_k<<<(BHN * LP * 32 + 255) / 256, 256>>>();
    softmax_k<<<BHN * LP, 256>>>();

    // 4) attn @ PV (+residual)
    {
        OpAV op; op.M = LP; op.N = HD; op.K = LPP;
        gemm_tc<<<dim3((HD + 127) / 128, (LP + 127) / 128, BHN), 128, SMEM_DYN>>>(op);
    }

    // 5) output projection + bias + PX, then LayerNorm
    {
        OpY op; op.bd = bd; op.M = BATCH * LP; op.N = DM; op.K = NHEAD * HD;
        gemm_tc<<<dim3((DM + 127) / 128, (op.M + 127) / 128, 1), 128, SMEM_DYN>>>(op);
    }
    ln_k<<<BATCH * LP, 128>>>(gamma, beta, out);
}